// round 3
// baseline (speedup 1.0000x reference)
#include <cuda_runtime.h>
#include <math.h>

#define BB    64
#define POMO  200
#define PROB  200
#define NNODE 201
#define EMB   512
#define NH    16
#define HD    32

// ---------------------------------------------------------------------------
// Scratch (static __device__ arrays; no allocations allowed)
// ---------------------------------------------------------------------------
__device__ float g_K [BB * NNODE * EMB];   // K projection  (b*201+n, 512)
__device__ float g_V [BB * NNODE * EMB];   // V projection
__device__ float g_Q [BB * POMO  * EMB];   // Q = q1@Wqf + last@Wql
__device__ float g_O [BB * POMO  * EMB];   // attention out_concat
__device__ float g_MH[BB * POMO  * EMB];   // mh_atten_out

// ---------------------------------------------------------------------------
// Generic NN GEMM:  C[M,N] = A[M,K] @ B[K,N]  (+ optional A2@B2, + bias)
// BM=BN=64, BK=16, 256 threads, 4x4 microtile. M%64==0, N%64==0, K%16==0.
// ---------------------------------------------------------------------------
__global__ __launch_bounds__(256) void gemm_nn_kernel(
    const float* __restrict__ A,  const float* __restrict__ B,
    const float* __restrict__ A2, const float* __restrict__ B2,
    const float* __restrict__ bias, float* __restrict__ C,
    int M, int N, int K)
{
    __shared__ float As[16][68];   // k-major (transposed on store)
    __shared__ float Bs[16][68];   // k-major (natural)

    const int tid  = threadIdx.x;
    const int bm   = blockIdx.y * 64;
    const int bn   = blockIdx.x * 64;
    const int la_r = tid >> 2;            // 0..63 (A row within tile)
    const int la_k = (tid & 3) << 2;      // 0,4,8,12
    const int lb_k = tid >> 4;            // 0..15
    const int lb_c = (tid & 15) << 2;     // 0..60
    const int ty   = tid >> 4;            // 0..15
    const int tx   = tid & 15;            // 0..15

    float acc[4][4];
#pragma unroll
    for (int i = 0; i < 4; ++i)
#pragma unroll
        for (int j = 0; j < 4; ++j) acc[i][j] = 0.f;

    for (int pass = 0; pass < 2; ++pass) {
        const float* Ap = pass ? A2 : A;
        const float* Bp = pass ? B2 : B;
        if (Ap == nullptr) break;

        for (int k0 = 0; k0 < K; k0 += 16) {
            float4 av = *(const float4*)(Ap + (size_t)(bm + la_r) * K + k0 + la_k);
            float4 bv = *(const float4*)(Bp + (size_t)(k0 + lb_k) * N + bn + lb_c);
            __syncthreads();
            As[la_k + 0][la_r] = av.x;
            As[la_k + 1][la_r] = av.y;
            As[la_k + 2][la_r] = av.z;
            As[la_k + 3][la_r] = av.w;
            *(float4*)&Bs[lb_k][lb_c] = bv;
            __syncthreads();
#pragma unroll
            for (int kk = 0; kk < 16; ++kk) {
                float4 a = *(const float4*)&As[kk][ty << 2];
                float4 b = *(const float4*)&Bs[kk][tx << 2];
                float ar[4] = {a.x, a.y, a.z, a.w};
                float br[4] = {b.x, b.y, b.z, b.w};
#pragma unroll
                for (int i = 0; i < 4; ++i)
#pragma unroll
                    for (int j = 0; j < 4; ++j)
                        acc[i][j] = fmaf(ar[i], br[j], acc[i][j]);
            }
        }
    }

    float bb[4] = {0.f, 0.f, 0.f, 0.f};
    if (bias) {
#pragma unroll
        for (int j = 0; j < 4; ++j) bb[j] = bias[bn + (tx << 2) + j];
    }
#pragma unroll
    for (int i = 0; i < 4; ++i) {
        float4 o;
        o.x = acc[i][0] + bb[0];
        o.y = acc[i][1] + bb[1];
        o.z = acc[i][2] + bb[2];
        o.w = acc[i][3] + bb[3];
        *(float4*)(C + (size_t)(bm + (ty << 2) + i) * N + bn + (tx << 2)) = o;
    }
}

// ---------------------------------------------------------------------------
// Multi-head attention, flash-style (online softmax, no score buffer).
// One block per (b,h); one thread per query row; K/V tile in smem.
// ---------------------------------------------------------------------------
__global__ __launch_bounds__(256, 2) void attn_kernel(
    const float* __restrict__ Q, const float* __restrict__ Kb,
    const float* __restrict__ Vb, const float* __restrict__ mask,
    float* __restrict__ O)
{
    extern __shared__ float sm[];
    float* sK = sm;                    // NNODE*HD
    float* sV = sm + NNODE * HD;       // NNODE*HD

    const int b = blockIdx.x >> 4;
    const int h = blockIdx.x & 15;
    const float* Kp = Kb + (size_t)b * NNODE * EMB + h * HD;
    const float* Vp = Vb + (size_t)b * NNODE * EMB + h * HD;

    for (int idx = threadIdx.x; idx < NNODE * 8; idx += 256) {
        int n  = idx >> 3;
        int d4 = (idx & 7) << 2;
        *(float4*)(sK + n * HD + d4) = *(const float4*)(Kp + (size_t)n * EMB + d4);
        *(float4*)(sV + n * HD + d4) = *(const float4*)(Vp + (size_t)n * EMB + d4);
    }
    __syncthreads();

    const int n = threadIdx.x;
    if (n >= POMO) return;

    float q[HD];
    const float* Qp = Q + (size_t)(b * POMO + n) * EMB + h * HD;
#pragma unroll
    for (int d4 = 0; d4 < 8; ++d4) {
        float4 t = *(const float4*)(Qp + (d4 << 2));
        q[d4 * 4 + 0] = t.x; q[d4 * 4 + 1] = t.y;
        q[d4 * 4 + 2] = t.z; q[d4 * 4 + 3] = t.w;
    }

    const float* mrow = mask + (size_t)(b * POMO + n) * PROB;
    const float scale = 0.17677669529663687f;   // 1/sqrt(32)

    float mx = -1e30f, l = 0.f;
    float acc[HD];
#pragma unroll
    for (int d = 0; d < HD; ++d) acc[d] = 0.f;

    for (int m = 0; m < NNODE; ++m) {
        const float4* kr4 = (const float4*)(sK + m * HD);
        float s = 0.f;
#pragma unroll
        for (int d4 = 0; d4 < 8; ++d4) {
            float4 kv = kr4[d4];
            s = fmaf(q[d4 * 4 + 0], kv.x, s);
            s = fmaf(q[d4 * 4 + 1], kv.y, s);
            s = fmaf(q[d4 * 4 + 2], kv.z, s);
            s = fmaf(q[d4 * 4 + 3], kv.w, s);
        }
        s *= scale;
        if (m < PROB) s += mrow[m];

        if (s > mx) {
            float sc = __expf(mx - s);
            l *= sc;
#pragma unroll
            for (int d = 0; d < HD; ++d) acc[d] *= sc;
            mx = s;
        }
        float p = __expf(s - mx);
        l += p;
        const float4* vr4 = (const float4*)(sV + m * HD);
#pragma unroll
        for (int d4 = 0; d4 < 8; ++d4) {
            float4 vv = vr4[d4];
            acc[d4 * 4 + 0] = fmaf(p, vv.x, acc[d4 * 4 + 0]);
            acc[d4 * 4 + 1] = fmaf(p, vv.y, acc[d4 * 4 + 1]);
            acc[d4 * 4 + 2] = fmaf(p, vv.z, acc[d4 * 4 + 2]);
            acc[d4 * 4 + 3] = fmaf(p, vv.w, acc[d4 * 4 + 3]);
        }
    }

    float inv = 1.f / l;
    float* Op = O + (size_t)(b * POMO + n) * EMB + h * HD;
#pragma unroll
    for (int d4 = 0; d4 < 8; ++d4) {
        float4 t;
        t.x = acc[d4 * 4 + 0] * inv;
        t.y = acc[d4 * 4 + 1] * inv;
        t.z = acc[d4 * 4 + 2] * inv;
        t.w = acc[d4 * 4 + 3] * inv;
        *(float4*)(Op + (d4 << 2)) = t;
    }
}

// ---------------------------------------------------------------------------
// score2 = (MH[b] @ nodes[b][:200]^T) / SQRT_EMB -> 10*tanh + mask, into out.
// NT GEMM, 64x64 tile with edge guards (200 rows/cols).
// ---------------------------------------------------------------------------
__global__ __launch_bounds__(256) void score2_kernel(
    const float* __restrict__ MH, const float* __restrict__ nodes,
    const float* __restrict__ mask, float* __restrict__ out)
{
    __shared__ float As[16][68];
    __shared__ float Bs[16][68];

    const int tid = threadIdx.x;
    const int b   = blockIdx.z;
    const int bm  = blockIdx.y * 64;
    const int bn  = blockIdx.x * 64;
    const float* A  = MH    + (size_t)b * POMO  * EMB;
    const float* Bm = nodes + (size_t)b * NNODE * EMB;

    const int lr = tid >> 2;           // 0..63
    const int lk = (tid & 3) << 2;     // 0,4,8,12
    const int ty = tid >> 4, tx = tid & 15;

    const bool a_ok = (bm + lr) < POMO;
    const bool b_ok = (bn + lr) < PROB;

    float acc[4][4];
#pragma unroll
    for (int i = 0; i < 4; ++i)
#pragma unroll
        for (int j = 0; j < 4; ++j) acc[i][j] = 0.f;

    for (int k0 = 0; k0 < EMB; k0 += 16) {
        float4 av = a_ok ? *(const float4*)(A  + (size_t)(bm + lr) * EMB + k0 + lk)
                         : make_float4(0.f, 0.f, 0.f, 0.f);
        float4 bv = b_ok ? *(const float4*)(Bm + (size_t)(bn + lr) * EMB + k0 + lk)
                         : make_float4(0.f, 0.f, 0.f, 0.f);
        __syncthreads();
        As[lk + 0][lr] = av.x; As[lk + 1][lr] = av.y;
        As[lk + 2][lr] = av.z; As[lk + 3][lr] = av.w;
        Bs[lk + 0][lr] = bv.x; Bs[lk + 1][lr] = bv.y;
        Bs[lk + 2][lr] = bv.z; Bs[lk + 3][lr] = bv.w;
        __syncthreads();
#pragma unroll
        for (int kk = 0; kk < 16; ++kk) {
            float4 a = *(const float4*)&As[kk][ty << 2];
            float4 b4 = *(const float4*)&Bs[kk][tx << 2];
            float ar[4] = {a.x, a.y, a.z, a.w};
            float br[4] = {b4.x, b4.y, b4.z, b4.w};
#pragma unroll
            for (int i = 0; i < 4; ++i)
#pragma unroll
                for (int j = 0; j < 4; ++j)
                    acc[i][j] = fmaf(ar[i], br[j], acc[i][j]);
        }
    }

    const float inv_sqrt_emb = 0.04419417382415922f;  // 1/22.627416997969522
#pragma unroll
    for (int i = 0; i < 4; ++i) {
        int m = bm + (ty << 2) + i;
        if (m >= POMO) continue;
#pragma unroll
        for (int j = 0; j < 4; ++j) {
            int nn = bn + (tx << 2) + j;
            if (nn >= PROB) continue;
            size_t off = (size_t)(b * POMO + m) * PROB + nn;
            float s = acc[i][j] * inv_sqrt_emb;
            out[off] = 10.f * tanhf(s) + mask[off];
        }
    }
}

// ---------------------------------------------------------------------------
// In-place row softmax over 200 columns, one warp per row.
// ---------------------------------------------------------------------------
__global__ __launch_bounds__(256) void softmax_kernel(float* __restrict__ out)
{
    const int row  = blockIdx.x * 8 + (threadIdx.x >> 5);
    const int lane = threadIdx.x & 31;
    float* p = out + (size_t)row * PROB;

    float v[7];
    float mx = -1e30f;
#pragma unroll
    for (int i = 0; i < 7; ++i) {
        int c = lane + (i << 5);
        v[i] = (c < PROB) ? p[c] : -1e30f;
        mx = fmaxf(mx, v[i]);
    }
#pragma unroll
    for (int off = 16; off; off >>= 1)
        mx = fmaxf(mx, __shfl_xor_sync(0xffffffffu, mx, off));

    float sum = 0.f;
#pragma unroll
    for (int i = 0; i < 7; ++i) { v[i] = __expf(v[i] - mx); sum += v[i]; }
#pragma unroll
    for (int off = 16; off; off >>= 1)
        sum += __shfl_xor_sync(0xffffffffu, sum, off);

    float inv = 1.f / sum;
#pragma unroll
    for (int i = 0; i < 7; ++i) {
        int c = lane + (i << 5);
        if (c < PROB) p[c] = v[i] * inv;
    }
}

// ---------------------------------------------------------------------------
// Launch
// ---------------------------------------------------------------------------
extern "C" void kernel_launch(void* const* d_in, const int* in_sizes, int n_in,
                              void* d_out, int out_size)
{
    const float* nodes = (const float*)d_in[0];
    const float* q1    = (const float*)d_in[1];
    const float* lastn = (const float*)d_in[2];
    const float* mask  = (const float*)d_in[3];
    const float* Wqf   = (const float*)d_in[4];
    const float* Wql   = (const float*)d_in[5];
    const float* Wk    = (const float*)d_in[6];
    const float* Wv    = (const float*)d_in[7];
    const float* Wc    = (const float*)d_in[8];
    const float* bc    = (const float*)d_in[9];
    float* out = (float*)d_out;

    float *Kb, *Vb, *Qb, *Ob, *MHb;
    cudaGetSymbolAddress((void**)&Kb,  g_K);
    cudaGetSymbolAddress((void**)&Vb,  g_V);
    cudaGetSymbolAddress((void**)&Qb,  g_Q);
    cudaGetSymbolAddress((void**)&Ob,  g_O);
    cudaGetSymbolAddress((void**)&MHb, g_MH);

    const int attn_smem = NNODE * HD * 2 * (int)sizeof(float);  // 51456 B
    cudaFuncSetAttribute(attn_kernel,
                         cudaFuncAttributeMaxDynamicSharedMemorySize, attn_smem);

    dim3 gKV(EMB / 64, (BB * NNODE) / 64);   // 8 x 201
    gemm_nn_kernel<<<gKV, 256>>>(nodes, Wk, nullptr, nullptr, nullptr, Kb,
                                 BB * NNODE, EMB, EMB);
    gemm_nn_kernel<<<gKV, 256>>>(nodes, Wv, nullptr, nullptr, nullptr, Vb,
                                 BB * NNODE, EMB, EMB);

    dim3 gQ(EMB / 64, (BB * POMO) / 64);     // 8 x 200
    gemm_nn_kernel<<<gQ, 256>>>(q1, Wqf, lastn, Wql, nullptr, Qb,
                                BB * POMO, EMB, EMB);

    attn_kernel<<<BB * NH, 256, attn_smem>>>(Qb, Kb, Vb, mask, Ob);

    gemm_nn_kernel<<<gQ, 256>>>(Ob, Wc, nullptr, nullptr, bc, MHb,
                                BB * POMO, EMB, EMB);

    dim3 gS(4, 4, BB);
    score2_kernel<<<gS, 256>>>(MHb, nodes, mask, out);

    softmax_kernel<<<(BB * POMO) / 8, 256>>>(out);
}

// round 5
// speedup vs baseline: 1.0972x; 1.0972x over previous
#include <cuda_runtime.h>
#include <math.h>

#define BB    64
#define POMO  200
#define PROB  200
#define NNODE 201
#define EMB   512
#define NH    16
#define HD    32

// ---------------------------------------------------------------------------
// Scratch
// ---------------------------------------------------------------------------
__device__ float g_K [BB * NNODE * EMB];
__device__ float g_V [BB * NNODE * EMB];
__device__ float g_Q [BB * POMO  * EMB];
__device__ float g_O [BB * POMO  * EMB];
__device__ float g_MH[BB * POMO  * EMB];

// ---------------------------------------------------------------------------
// Helpers: tf32 convert, mma.sync, packed f32x2
// ---------------------------------------------------------------------------
__device__ __forceinline__ float to_tf32(float x) {
    unsigned u;
    asm("cvt.rna.tf32.f32 %0, %1;" : "=r"(u) : "f"(x));
    return __uint_as_float(u);
}

__device__ __forceinline__ void mma_tf32(float* c, const float* a, const float* b) {
    asm volatile(
        "mma.sync.aligned.m16n8k8.row.col.f32.tf32.tf32.f32 "
        "{%0,%1,%2,%3}, {%4,%5,%6,%7}, {%8,%9}, {%0,%1,%2,%3};\n"
        : "+f"(c[0]), "+f"(c[1]), "+f"(c[2]), "+f"(c[3])
        : "r"(__float_as_uint(a[0])), "r"(__float_as_uint(a[1])),
          "r"(__float_as_uint(a[2])), "r"(__float_as_uint(a[3])),
          "r"(__float_as_uint(b[0])), "r"(__float_as_uint(b[1])));
}

typedef unsigned long long u64;
__device__ __forceinline__ u64 pack2(float lo, float hi) {
    u64 r; asm("mov.b64 %0, {%1,%2};" : "=l"(r) : "f"(lo), "f"(hi)); return r;
}
__device__ __forceinline__ void unpack2(u64 v, float& lo, float& hi) {
    asm("mov.b64 {%0,%1}, %2;" : "=f"(lo), "=f"(hi) : "l"(v));
}
__device__ __forceinline__ u64 ffma2(u64 a, u64 b, u64 c) {
    u64 d; asm("fma.rn.f32x2 %0,%1,%2,%3;" : "=l"(d) : "l"(a), "l"(b), "l"(c)); return d;
}
__device__ __forceinline__ u64 fmul2(u64 a, u64 b) {
    u64 d; asm("mul.rn.f32x2 %0,%1,%2;" : "=l"(d) : "l"(a), "l"(b)); return d;
}
__device__ __forceinline__ u64 fadd2(u64 a, u64 b) {
    u64 d; asm("add.rn.f32x2 %0,%1,%2;" : "=l"(d) : "l"(a), "l"(b)); return d;
}

// ---------------------------------------------------------------------------
// tf32 tensor-core NN GEMM: C[M,N] = A[M,K]@B[K,N] (+A2@B2) (+bias)
// Block tile 64x128, BK=16, 256 threads, 8 warps (2m x 4n), warp tile 32x32.
// Requires M%64==0, N%128==0, K%16==0.
// ---------------------------------------------------------------------------
__global__ __launch_bounds__(256) void gemm_tf32(
    const float* __restrict__ A,  const float* __restrict__ B,
    const float* __restrict__ A2, const float* __restrict__ B2,
    const float* __restrict__ bias, float* __restrict__ C,
    int M, int N, int K)
{
    __shared__ float As[2][16][68];    // k-major (transposed A)
    __shared__ float Bs[2][16][132];   // k-major (natural B)

    const int tid  = threadIdx.x;
    const int lane = tid & 31, warp = tid >> 5;
    const int g    = lane >> 2, tig = lane & 3;
    const int wm   = warp >> 2, wn  = warp & 3;
    const int bm   = blockIdx.y * 64, bn = blockIdx.x * 128;
    const int ar   = tid >> 2, ak = (tid & 3) << 2;
    const int bk0  = tid >> 5, bn4 = (tid & 31) << 2;

    float acc[2][4][4];
#pragma unroll
    for (int i = 0; i < 2; ++i)
#pragma unroll
        for (int j = 0; j < 4; ++j)
#pragma unroll
            for (int t = 0; t < 4; ++t) acc[i][j][t] = 0.f;

    for (int pass = 0; pass < 2; ++pass) {
        const float* Ap = pass ? A2 : A;
        const float* Bp = pass ? B2 : B;
        if (Ap == nullptr) break;
        const int S = K / 16;

        // prologue: stage k-step 0 into buffer 0
        {
            float4 av = *(const float4*)(Ap + (size_t)(bm + ar) * K + ak);
            As[0][ak + 0][ar] = to_tf32(av.x);
            As[0][ak + 1][ar] = to_tf32(av.y);
            As[0][ak + 2][ar] = to_tf32(av.z);
            As[0][ak + 3][ar] = to_tf32(av.w);
            float4 b0 = *(const float4*)(Bp + (size_t)bk0 * N + bn + bn4);
            float4 b1 = *(const float4*)(Bp + (size_t)(bk0 + 8) * N + bn + bn4);
            float4 c0 = make_float4(to_tf32(b0.x), to_tf32(b0.y), to_tf32(b0.z), to_tf32(b0.w));
            float4 c1 = make_float4(to_tf32(b1.x), to_tf32(b1.y), to_tf32(b1.z), to_tf32(b1.w));
            *(float4*)&Bs[0][bk0][bn4]     = c0;
            *(float4*)&Bs[0][bk0 + 8][bn4] = c1;
        }
        __syncthreads();

        for (int s = 0; s < S; ++s) {
            const int cur = s & 1;
            float4 av, b0, b1;
            if (s + 1 < S) {
                const int k0 = (s + 1) * 16;
                av = *(const float4*)(Ap + (size_t)(bm + ar) * K + k0 + ak);
                b0 = *(const float4*)(Bp + (size_t)(k0 + bk0) * N + bn + bn4);
                b1 = *(const float4*)(Bp + (size_t)(k0 + bk0 + 8) * N + bn + bn4);
            }
#pragma unroll
            for (int ks = 0; ks < 2; ++ks) {
                const int kk = ks * 8;
                float afr[2][4], bfr[4][2];
#pragma unroll
                for (int mf = 0; mf < 2; ++mf) {
                    const int mr = wm * 32 + mf * 16 + g;
                    afr[mf][0] = As[cur][kk + tig    ][mr];
                    afr[mf][1] = As[cur][kk + tig    ][mr + 8];
                    afr[mf][2] = As[cur][kk + tig + 4][mr];
                    afr[mf][3] = As[cur][kk + tig + 4][mr + 8];
                }
#pragma unroll
                for (int nf = 0; nf < 4; ++nf) {
                    const int nc = wn * 32 + nf * 8 + g;
                    bfr[nf][0] = Bs[cur][kk + tig    ][nc];
                    bfr[nf][1] = Bs[cur][kk + tig + 4][nc];
                }
#pragma unroll
                for (int mf = 0; mf < 2; ++mf)
#pragma unroll
                    for (int nf = 0; nf < 4; ++nf)
                        mma_tf32(acc[mf][nf], afr[mf], bfr[nf]);
            }
            if (s + 1 < S) {
                const int nx = cur ^ 1;
                As[nx][ak + 0][ar] = to_tf32(av.x);
                As[nx][ak + 1][ar] = to_tf32(av.y);
                As[nx][ak + 2][ar] = to_tf32(av.z);
                As[nx][ak + 3][ar] = to_tf32(av.w);
                float4 c0 = make_float4(to_tf32(b0.x), to_tf32(b0.y), to_tf32(b0.z), to_tf32(b0.w));
                float4 c1 = make_float4(to_tf32(b1.x), to_tf32(b1.y), to_tf32(b1.z), to_tf32(b1.w));
                *(float4*)&Bs[nx][bk0][bn4]     = c0;
                *(float4*)&Bs[nx][bk0 + 8][bn4] = c1;
                __syncthreads();
            }
        }
        __syncthreads();   // pass boundary: protect buffers before next prologue
    }

    const int mbase = bm + wm * 32;
    const int nbase = bn + wn * 32;
#pragma unroll
    for (int nf = 0; nf < 4; ++nf) {
        const int c0 = nbase + nf * 8 + 2 * tig;
        float bb0 = 0.f, bb1 = 0.f;
        if (bias) { bb0 = bias[c0]; bb1 = bias[c0 + 1]; }
#pragma unroll
        for (int mf = 0; mf < 2; ++mf) {
            const int r0 = mbase + mf * 16 + g;
            float2 v;
            v.x = acc[mf][nf][0] + bb0; v.y = acc[mf][nf][1] + bb1;
            *(float2*)(C + (size_t)r0 * N + c0) = v;
            v.x = acc[mf][nf][2] + bb0; v.y = acc[mf][nf][3] + bb1;
            *(float2*)(C + (size_t)(r0 + 8) * N + c0) = v;
        }
    }
}

// ---------------------------------------------------------------------------
// score2: per-batch NT GEMM MH[200,512] @ nodes[200,512]^T with
// /sqrt(EMB), 10*tanh, +mask epilogue. tf32 mma, tile 64x128 with guards.
// ---------------------------------------------------------------------------
__global__ __launch_bounds__(256) void score2_tf32(
    const float* __restrict__ MH, const float* __restrict__ nodes,
    const float* __restrict__ mask, float* __restrict__ out)
{
    __shared__ float As[2][16][68];
    __shared__ float Bs[2][16][132];

    const int tid  = threadIdx.x;
    const int lane = tid & 31, warp = tid >> 5;
    const int g    = lane >> 2, tig = lane & 3;
    const int wm   = warp >> 2, wn  = warp & 3;
    const int b    = blockIdx.z;
    const int bm   = blockIdx.y * 64, bn = blockIdx.x * 128;
    const float* A  = MH    + (size_t)b * POMO  * EMB;
    const float* Bn = nodes + (size_t)b * NNODE * EMB;

    const int ar = tid >> 2, ak = (tid & 3) << 2;   // A transpose load
    const int nl = tid >> 2, kc = (tid & 3) << 2;   // B transpose load (rows nl, nl+64)

    const bool a_ok  = (bm + ar)      < POMO;
    const bool b_ok0 = (bn + nl)      < PROB;
    const bool b_ok1 = (bn + nl + 64) < PROB;

    float acc[2][4][4];
#pragma unroll
    for (int i = 0; i < 2; ++i)
#pragma unroll
        for (int j = 0; j < 4; ++j)
#pragma unroll
            for (int t = 0; t < 4; ++t) acc[i][j][t] = 0.f;

    const float4 z4 = make_float4(0.f, 0.f, 0.f, 0.f);
    const int S = EMB / 16;

    // prologue
    {
        float4 av = a_ok  ? *(const float4*)(A  + (size_t)(bm + ar) * EMB + ak)      : z4;
        float4 b0 = b_ok0 ? *(const float4*)(Bn + (size_t)(bn + nl) * EMB + kc)      : z4;
        float4 b1 = b_ok1 ? *(const float4*)(Bn + (size_t)(bn + nl + 64) * EMB + kc) : z4;
        As[0][ak + 0][ar] = to_tf32(av.x); As[0][ak + 1][ar] = to_tf32(av.y);
        As[0][ak + 2][ar] = to_tf32(av.z); As[0][ak + 3][ar] = to_tf32(av.w);
        Bs[0][kc + 0][nl] = to_tf32(b0.x); Bs[0][kc + 1][nl] = to_tf32(b0.y);
        Bs[0][kc + 2][nl] = to_tf32(b0.z); Bs[0][kc + 3][nl] = to_tf32(b0.w);
        Bs[0][kc + 0][nl + 64] = to_tf32(b1.x); Bs[0][kc + 1][nl + 64] = to_tf32(b1.y);
        Bs[0][kc + 2][nl + 64] = to_tf32(b1.z); Bs[0][kc + 3][nl + 64] = to_tf32(b1.w);
    }
    __syncthreads();

    for (int s = 0; s < S; ++s) {
        const int cur = s & 1;
        float4 av, b0, b1;
        if (s + 1 < S) {
            const int k0 = (s + 1) * 16;
            av = a_ok  ? *(const float4*)(A  + (size_t)(bm + ar) * EMB + k0 + ak)      : z4;
            b0 = b_ok0 ? *(const float4*)(Bn + (size_t)(bn + nl) * EMB + k0 + kc)      : z4;
            b1 = b_ok1 ? *(const float4*)(Bn + (size_t)(bn + nl + 64) * EMB + k0 + kc) : z4;
        }
#pragma unroll
        for (int ks = 0; ks < 2; ++ks) {
            const int kk = ks * 8;
            float afr[2][4], bfr[4][2];
#pragma unroll
            for (int mf = 0; mf < 2; ++mf) {
                const int mr = wm * 32 + mf * 16 + g;
                afr[mf][0] = As[cur][kk + tig    ][mr];
                afr[mf][1] = As[cur][kk + tig    ][mr + 8];
                afr[mf][2] = As[cur][kk + tig + 4][mr];
                afr[mf][3] = As[cur][kk + tig + 4][mr + 8];
            }
#pragma unroll
            for (int nf = 0; nf < 4; ++nf) {
                const int nc = wn * 32 + nf * 8 + g;
                bfr[nf][0] = Bs[cur][kk + tig    ][nc];
                bfr[nf][1] = Bs[cur][kk + tig + 4][nc];
            }
#pragma unroll
            for (int mf = 0; mf < 2; ++mf)
#pragma unroll
                for (int nf = 0; nf < 4; ++nf)
                    mma_tf32(acc[mf][nf], afr[mf], bfr[nf]);
        }
        if (s + 1 < S) {
            const int nx = cur ^ 1;
            As[nx][ak + 0][ar] = to_tf32(av.x); As[nx][ak + 1][ar] = to_tf32(av.y);
            As[nx][ak + 2][ar] = to_tf32(av.z); As[nx][ak + 3][ar] = to_tf32(av.w);
            Bs[nx][kc + 0][nl] = to_tf32(b0.x); Bs[nx][kc + 1][nl] = to_tf32(b0.y);
            Bs[nx][kc + 2][nl] = to_tf32(b0.z); Bs[nx][kc + 3][nl] = to_tf32(b0.w);
            Bs[nx][kc + 0][nl + 64] = to_tf32(b1.x); Bs[nx][kc + 1][nl + 64] = to_tf32(b1.y);
            Bs[nx][kc + 2][nl + 64] = to_tf32(b1.z); Bs[nx][kc + 3][nl + 64] = to_tf32(b1.w);
            __syncthreads();
        }
    }

    const float inv_sqrt_emb = 0.04419417382415922f;
    const int mbase = bm + wm * 32;
    const int nbase = bn + wn * 32;
#pragma unroll
    for (int mf = 0; mf < 2; ++mf) {
#pragma unroll
        for (int nf = 0; nf < 4; ++nf) {
#pragma unroll
            for (int t = 0; t < 4; ++t) {
                const int r = mbase + mf * 16 + g + ((t >> 1) << 3);
                const int c = nbase + nf * 8 + 2 * tig + (t & 1);
                if (r < POMO && c < PROB) {
                    const size_t off = ((size_t)b * POMO + r) * PROB + c;
                    out[off] = 10.f * tanhf(acc[mf][nf][t] * inv_sqrt_emb) + mask[off];
                }
            }
        }
    }
}

// ---------------------------------------------------------------------------
// Attention, flash-style, packed f32x2 math.
// ---------------------------------------------------------------------------
__global__ __launch_bounds__(256, 2) void attn_kernel(
    const float* __restrict__ Q, const float* __restrict__ Kb,
    const float* __restrict__ Vb, const float* __restrict__ mask,
    float* __restrict__ O)
{
    extern __shared__ float sm[];
    float* sK = sm;
    float* sV = sm + NNODE * HD;

    const int b = blockIdx.x >> 4;
    const int h = blockIdx.x & 15;
    const float* Kp = Kb + (size_t)b * NNODE * EMB + h * HD;
    const float* Vp = Vb + (size_t)b * NNODE * EMB + h * HD;

    for (int idx = threadIdx.x; idx < NNODE * 8; idx += 256) {
        int n  = idx >> 3;
        int d4 = (idx & 7) << 2;
        *(float4*)(sK + n * HD + d4) = *(const float4*)(Kp + (size_t)n * EMB + d4);
        *(float4*)(sV + n * HD + d4) = *(const float4*)(Vp + (size_t)n * EMB + d4);
    }
    __syncthreads();

    const int n = threadIdx.x;
    if (n >= POMO) return;

    const float scale = 0.17677669529663687f;   // 1/sqrt(32)
    u64 q2[16];
    const float* Qp = Q + (size_t)(b * POMO + n) * EMB + h * HD;
#pragma unroll
    for (int d4 = 0; d4 < 8; ++d4) {
        float4 t = *(const float4*)(Qp + (d4 << 2));
        q2[2 * d4 + 0] = pack2(t.x * scale, t.y * scale);
        q2[2 * d4 + 1] = pack2(t.z * scale, t.w * scale);
    }

    const float* mrow = mask + (size_t)(b * POMO + n) * PROB;

    float mx = -1e30f, l = 0.f;
    u64 acc2[16];
#pragma unroll
    for (int i = 0; i < 16; ++i) acc2[i] = 0ULL;

    for (int m = 0; m < NNODE; ++m) {
        const float4* kr = (const float4*)(sK + m * HD);
        u64 s0 = 0ULL, s1 = 0ULL, s2 = 0ULL, s3 = 0ULL;
#pragma unroll
        for (int d4 = 0; d4 < 8; ++d4) {
            float4 kv = kr[d4];
            u64 k01 = pack2(kv.x, kv.y);
            u64 k23 = pack2(kv.z, kv.w);
            if (d4 & 1) {
                s2 = ffma2(q2[2 * d4 + 0], k01, s2);
                s3 = ffma2(q2[2 * d4 + 1], k23, s3);
            } else {
                s0 = ffma2(q2[2 * d4 + 0], k01, s0);
                s1 = ffma2(q2[2 * d4 + 1], k23, s1);
            }
        }
        u64 st = fadd2(fadd2(s0, s1), fadd2(s2, s3));
        float slo, shi;
        unpack2(st, slo, shi);
        float s = slo + shi;
        if (m < PROB) s += mrow[m];

        if (s > mx) {
            float sc = __expf(mx - s);
            l *= sc;
            u64 sc2 = pack2(sc, sc);
#pragma unroll
            for (int i = 0; i < 16; ++i) acc2[i] = fmul2(acc2[i], sc2);
            mx = s;
        }
        float p = __expf(s - mx);
        l += p;
        u64 p2 = pack2(p, p);
        const float4* vr = (const float4*)(sV + m * HD);
#pragma unroll
        for (int d4 = 0; d4 < 8; ++d4) {
            float4 vv = vr[d4];
            acc2[2 * d4 + 0] = ffma2(p2, pack2(vv.x, vv.y), acc2[2 * d4 + 0]);
            acc2[2 * d4 + 1] = ffma2(p2, pack2(vv.z, vv.w), acc2[2 * d4 + 1]);
        }
    }

    const float inv = 1.f / l;
    float* Op = O + (size_t)(b * POMO + n) * EMB + h * HD;
#pragma unroll
    for (int d4 = 0; d4 < 8; ++d4) {
        float a0, a1, a2, a3;
        unpack2(acc2[2 * d4 + 0], a0, a1);
        unpack2(acc2[2 * d4 + 1], a2, a3);
        float4 t;
        t.x = a0 * inv; t.y = a1 * inv; t.z = a2 * inv; t.w = a3 * inv;
        *(float4*)(Op + (d4 << 2)) = t;
    }
}

// ---------------------------------------------------------------------------
// In-place row softmax over 200 columns, one warp per row.
// ---------------------------------------------------------------------------
__global__ __launch_bounds__(256) void softmax_kernel(float* __restrict__ out)
{
    const int row  = blockIdx.x * 8 + (threadIdx.x >> 5);
    const int lane = threadIdx.x & 31;
    float* p = out + (size_t)row * PROB;

    float v[7];
    float mx = -1e30f;
#pragma unroll
    for (int i = 0; i < 7; ++i) {
        int c = lane + (i << 5);
        v[i] = (c < PROB) ? p[c] : -1e30f;
        mx = fmaxf(mx, v[i]);
    }
#pragma unroll
    for (int off = 16; off; off >>= 1)
        mx = fmaxf(mx, __shfl_xor_sync(0xffffffffu, mx, off));

    float sum = 0.f;
#pragma unroll
    for (int i = 0; i < 7; ++i) { v[i] = __expf(v[i] - mx); sum += v[i]; }
#pragma unroll
    for (int off = 16; off; off >>= 1)
        sum += __shfl_xor_sync(0xffffffffu, sum, off);

    float inv = 1.f / sum;
#pragma unroll
    for (int i = 0; i < 7; ++i) {
        int c = lane + (i << 5);
        if (c < PROB) p[c] = v[i] * inv;
    }
}

// ---------------------------------------------------------------------------
// Launch
// ---------------------------------------------------------------------------
extern "C" void kernel_launch(void* const* d_in, const int* in_sizes, int n_in,
                              void* d_out, int out_size)
{
    const float* nodes = (const float*)d_in[0];
    const float* q1    = (const float*)d_in[1];
    const float* lastn = (const float*)d_in[2];
    const float* mask  = (const float*)d_in[3];
    const float* Wqf   = (const float*)d_in[4];
    const float* Wql   = (const float*)d_in[5];
    const float* Wk    = (const float*)d_in[6];
    const float* Wv    = (const float*)d_in[7];
    const float* Wc    = (const float*)d_in[8];
    const float* bc    = (const float*)d_in[9];
    float* out = (float*)d_out;

    float *Kb, *Vb, *Qb, *Ob, *MHb;
    cudaGetSymbolAddress((void**)&Kb,  g_K);
    cudaGetSymbolAddress((void**)&Vb,  g_V);
    cudaGetSymbolAddress((void**)&Qb,  g_Q);
    cudaGetSymbolAddress((void**)&Ob,  g_O);
    cudaGetSymbolAddress((void**)&MHb, g_MH);

    const int attn_smem = NNODE * HD * 2 * (int)sizeof(float);  // 51456 B
    cudaFuncSetAttribute(attn_kernel,
                         cudaFuncAttributeMaxDynamicSharedMemorySize, attn_smem);

    dim3 gKV(EMB / 128, (BB * NNODE) / 64);   // 4 x 201
    gemm_tf32<<<gKV, 256>>>(nodes, Wk, nullptr, nullptr, nullptr, Kb,
                            BB * NNODE, EMB, EMB);
    gemm_tf32<<<gKV, 256>>>(nodes, Wv, nullptr, nullptr, nullptr, Vb,
                            BB * NNODE, EMB, EMB);

    dim3 gQ(EMB / 128, (BB * POMO) / 64);     // 4 x 200
    gemm_tf32<<<gQ, 256>>>(q1, Wqf, lastn, Wql, nullptr, Qb,
                           BB * POMO, EMB, EMB);

    attn_kernel<<<BB * NH, 256, attn_smem>>>(Qb, Kb, Vb, mask, Ob);

    gemm_tf32<<<gQ, 256>>>(Ob, Wc, nullptr, nullptr, bc, MHb,
                           BB * POMO, EMB, EMB);

    dim3 gS(2, 4, BB);
    score2_tf32<<<gS, 256>>>(MHb, nodes, mask, out);

    softmax_kernel<<<(BB * POMO) / 8, 256>>>(out);
}

// round 6
// speedup vs baseline: 1.3536x; 1.2336x over previous
#include <cuda_runtime.h>
#include <math.h>

#define BB    64
#define POMO  200
#define PROB  200
#define NNODE 201
#define EMB   512
#define NH    16
#define HD    32

// ---------------------------------------------------------------------------
// Scratch
// ---------------------------------------------------------------------------
__device__ float g_K [BB * NNODE * EMB];
__device__ float g_V [BB * NNODE * EMB];
__device__ float g_Q [BB * POMO  * EMB];
__device__ float g_O [BB * POMO  * EMB];
__device__ float g_MH[BB * POMO  * EMB];

// ---------------------------------------------------------------------------
// Helpers
// ---------------------------------------------------------------------------
__device__ __forceinline__ float to_tf32(float x) {
    unsigned u;
    asm("cvt.rna.tf32.f32 %0, %1;" : "=r"(u) : "f"(x));
    return __uint_as_float(u);
}

__device__ __forceinline__ void mma_tf32(float* c, const float* a, const float* b) {
    asm volatile(
        "mma.sync.aligned.m16n8k8.row.col.f32.tf32.tf32.f32 "
        "{%0,%1,%2,%3}, {%4,%5,%6,%7}, {%8,%9}, {%0,%1,%2,%3};\n"
        : "+f"(c[0]), "+f"(c[1]), "+f"(c[2]), "+f"(c[3])
        : "r"(__float_as_uint(a[0])), "r"(__float_as_uint(a[1])),
          "r"(__float_as_uint(a[2])), "r"(__float_as_uint(a[3])),
          "r"(__float_as_uint(b[0])), "r"(__float_as_uint(b[1])));
}

__device__ __forceinline__ unsigned smem_u32(const void* p) {
    return (unsigned)__cvta_generic_to_shared(p);
}
__device__ __forceinline__ void cp16(unsigned d, const void* s) {
    asm volatile("cp.async.cg.shared.global [%0], [%1], 16;" :: "r"(d), "l"(s));
}
#define CP_COMMIT() asm volatile("cp.async.commit_group;")
#define CP_WAIT2()  asm volatile("cp.async.wait_group 2;")

// ---------------------------------------------------------------------------
// 3xTF32 pipelined GEMM: C[M,N] = A@B (+ A2@B2) (+bias)
// BM=BN=128, BK=16, 4-stage cp.async, 256 threads, warp tile 64x32.
// N % 128 == 0, K % 16 == 0; M guarded (row-clamp on load, guard on store).
// ---------------------------------------------------------------------------
#define ST     4
#define APITCH 20     // 128 rows x 16 k, padded -> conflict-free frag LDS
#define BPITCH 136    // 16 k x 128 n,  padded -> conflict-free frag LDS
#define ASTG   (128 * APITCH)
#define BSTG   (16  * BPITCH)

__global__ __launch_bounds__(256) void gemm3x(
    const float* __restrict__ A,  const float* __restrict__ B,
    const float* __restrict__ A2, const float* __restrict__ B2,
    const float* __restrict__ bias, float* __restrict__ C,
    int M, int N, int K)
{
    extern __shared__ float sm[];
    float* As = sm;                 // ST * ASTG
    float* Bs = sm + ST * ASTG;     // ST * BSTG

    const int tid  = threadIdx.x;
    const int lane = tid & 31, warp = tid >> 5;
    const int g    = lane >> 2, tig = lane & 3;
    const int wm   = warp >> 2;     // 0..1
    const int wn   = warp & 3;      // 0..3
    const int bm   = blockIdx.y * 128, bn = blockIdx.x * 128;

    const int SK = K / 16;
    const int S  = A2 ? 2 * SK : SK;

    // load thread mapping
    const int a_row = tid >> 2,        a_k4 = (tid & 3) << 2;   // +64 rows second chunk
    const int b_kr  = tid >> 5,        b_n4 = (tid & 31) << 2;  // +8 rows second chunk

    auto load_tile = [&](int st, int t) {
        const float* Ap = (t >= SK) ? A2 : A;
        const float* Bp = (t >= SK) ? B2 : B;
        const int k0 = ((t >= SK) ? t - SK : t) << 4;
        float* Ad = As + st * ASTG;
        float* Bd = Bs + st * BSTG;
        int r0 = bm + a_row;        if (r0 >= M) r0 = M - 1;
        int r1 = bm + a_row + 64;   if (r1 >= M) r1 = M - 1;
        cp16(smem_u32(Ad + a_row * APITCH + a_k4),
             Ap + (size_t)r0 * K + k0 + a_k4);
        cp16(smem_u32(Ad + (a_row + 64) * APITCH + a_k4),
             Ap + (size_t)r1 * K + k0 + a_k4);
        cp16(smem_u32(Bd + b_kr * BPITCH + b_n4),
             Bp + (size_t)(k0 + b_kr) * N + bn + b_n4);
        cp16(smem_u32(Bd + (b_kr + 8) * BPITCH + b_n4),
             Bp + (size_t)(k0 + b_kr + 8) * N + bn + b_n4);
    };

    float acc[4][4][4];
#pragma unroll
    for (int i = 0; i < 4; ++i)
#pragma unroll
        for (int j = 0; j < 4; ++j)
#pragma unroll
            for (int t = 0; t < 4; ++t) acc[i][j][t] = 0.f;

    // prologue: stages 0..ST-2
#pragma unroll
    for (int t = 0; t < ST - 1; ++t) {
        if (t < S) load_tile(t, t);
        CP_COMMIT();
    }

    for (int s = 0; s < S; ++s) {
        CP_WAIT2();
        __syncthreads();
        const int nt = s + ST - 1;
        if (nt < S) load_tile(nt & (ST - 1), nt);
        CP_COMMIT();

        const float* Asl = As + (s & (ST - 1)) * ASTG;
        const float* Bsl = Bs + (s & (ST - 1)) * BSTG;

#pragma unroll
        for (int ks = 0; ks < 2; ++ks) {
            const int kk = ks << 3;
            float ahi[4][4], alo[4][4], bhi[4][2], blo[4][2];
#pragma unroll
            for (int mf = 0; mf < 4; ++mf) {
                const int mr = wm * 64 + mf * 16 + g;
                float r0 = Asl[mr * APITCH + kk + tig];
                float r1 = Asl[(mr + 8) * APITCH + kk + tig];
                float r2 = Asl[mr * APITCH + kk + tig + 4];
                float r3 = Asl[(mr + 8) * APITCH + kk + tig + 4];
                ahi[mf][0] = to_tf32(r0); alo[mf][0] = r0 - ahi[mf][0];
                ahi[mf][1] = to_tf32(r1); alo[mf][1] = r1 - ahi[mf][1];
                ahi[mf][2] = to_tf32(r2); alo[mf][2] = r2 - ahi[mf][2];
                ahi[mf][3] = to_tf32(r3); alo[mf][3] = r3 - ahi[mf][3];
            }
#pragma unroll
            for (int nf = 0; nf < 4; ++nf) {
                const int nc = wn * 32 + nf * 8 + g;
                float r0 = Bsl[(kk + tig) * BPITCH + nc];
                float r1 = Bsl[(kk + tig + 4) * BPITCH + nc];
                bhi[nf][0] = to_tf32(r0); blo[nf][0] = r0 - bhi[nf][0];
                bhi[nf][1] = to_tf32(r1); blo[nf][1] = r1 - bhi[nf][1];
            }
            // three passes -> long independent chains on each acc
#pragma unroll
            for (int mf = 0; mf < 4; ++mf)
#pragma unroll
                for (int nf = 0; nf < 4; ++nf)
                    mma_tf32(acc[mf][nf], ahi[mf], bhi[nf]);
#pragma unroll
            for (int mf = 0; mf < 4; ++mf)
#pragma unroll
                for (int nf = 0; nf < 4; ++nf)
                    mma_tf32(acc[mf][nf], alo[mf], bhi[nf]);
#pragma unroll
            for (int mf = 0; mf < 4; ++mf)
#pragma unroll
                for (int nf = 0; nf < 4; ++nf)
                    mma_tf32(acc[mf][nf], ahi[mf], blo[nf]);
        }
    }

    // epilogue
#pragma unroll
    for (int nf = 0; nf < 4; ++nf) {
        const int c0 = bn + wn * 32 + nf * 8 + 2 * tig;
        float bb0 = 0.f, bb1 = 0.f;
        if (bias) { bb0 = bias[c0]; bb1 = bias[c0 + 1]; }
#pragma unroll
        for (int mf = 0; mf < 4; ++mf) {
            const int r0 = bm + wm * 64 + mf * 16 + g;
            if (r0 < M) {
                float2 v; v.x = acc[mf][nf][0] + bb0; v.y = acc[mf][nf][1] + bb1;
                *(float2*)(C + (size_t)r0 * N + c0) = v;
            }
            if (r0 + 8 < M) {
                float2 v; v.x = acc[mf][nf][2] + bb0; v.y = acc[mf][nf][3] + bb1;
                *(float2*)(C + (size_t)(r0 + 8) * N + c0) = v;
            }
        }
    }
}

// ---------------------------------------------------------------------------
// score2: per-batch NT GEMM MH[200,512] @ nodes[200,512]^T, 3xTF32,
// /sqrt(EMB) -> 10*tanh -> +mask epilogue. Tile 64x128 with guards.
// ---------------------------------------------------------------------------
__global__ __launch_bounds__(256) void score2_tf32(
    const float* __restrict__ MH, const float* __restrict__ nodes,
    const float* __restrict__ mask, float* __restrict__ out)
{
    __shared__ float As[2][16][68];
    __shared__ float Bs[2][16][132];

    const int tid  = threadIdx.x;
    const int lane = tid & 31, warp = tid >> 5;
    const int g    = lane >> 2, tig = lane & 3;
    const int wm   = warp >> 2, wn  = warp & 3;
    const int b    = blockIdx.z;
    const int bm   = blockIdx.y * 64, bn = blockIdx.x * 128;
    const float* A  = MH    + (size_t)b * POMO  * EMB;
    const float* Bn = nodes + (size_t)b * NNODE * EMB;

    const int ar = tid >> 2, ak = (tid & 3) << 2;
    const int nl = tid >> 2, kc = (tid & 3) << 2;

    const bool a_ok  = (bm + ar)      < POMO;
    const bool b_ok0 = (bn + nl)      < PROB;
    const bool b_ok1 = (bn + nl + 64) < PROB;

    float acc[2][4][4];
#pragma unroll
    for (int i = 0; i < 2; ++i)
#pragma unroll
        for (int j = 0; j < 4; ++j)
#pragma unroll
            for (int t = 0; t < 4; ++t) acc[i][j][t] = 0.f;

    const float4 z4 = make_float4(0.f, 0.f, 0.f, 0.f);
    const int S = EMB / 16;

    {
        float4 av = a_ok  ? *(const float4*)(A  + (size_t)(bm + ar) * EMB + ak)      : z4;
        float4 b0 = b_ok0 ? *(const float4*)(Bn + (size_t)(bn + nl) * EMB + kc)      : z4;
        float4 b1 = b_ok1 ? *(const float4*)(Bn + (size_t)(bn + nl + 64) * EMB + kc) : z4;
        As[0][ak + 0][ar] = av.x; As[0][ak + 1][ar] = av.y;
        As[0][ak + 2][ar] = av.z; As[0][ak + 3][ar] = av.w;
        Bs[0][kc + 0][nl] = b0.x; Bs[0][kc + 1][nl] = b0.y;
        Bs[0][kc + 2][nl] = b0.z; Bs[0][kc + 3][nl] = b0.w;
        Bs[0][kc + 0][nl + 64] = b1.x; Bs[0][kc + 1][nl + 64] = b1.y;
        Bs[0][kc + 2][nl + 64] = b1.z; Bs[0][kc + 3][nl + 64] = b1.w;
    }
    __syncthreads();

    for (int s = 0; s < S; ++s) {
        const int cur = s & 1;
        float4 av, b0, b1;
        if (s + 1 < S) {
            const int k0 = (s + 1) * 16;
            av = a_ok  ? *(const float4*)(A  + (size_t)(bm + ar) * EMB + k0 + ak)      : z4;
            b0 = b_ok0 ? *(const float4*)(Bn + (size_t)(bn + nl) * EMB + k0 + kc)      : z4;
            b1 = b_ok1 ? *(const float4*)(Bn + (size_t)(bn + nl + 64) * EMB + k0 + kc) : z4;
        }
#pragma unroll
        for (int ks = 0; ks < 2; ++ks) {
            const int kk = ks * 8;
            float ahi[2][4], alo[2][4], bhi[4][2], blo[4][2];
#pragma unroll
            for (int mf = 0; mf < 2; ++mf) {
                const int mr = wm * 32 + mf * 16 + g;
                float r0 = As[cur][kk + tig    ][mr];
                float r1 = As[cur][kk + tig    ][mr + 8];
                float r2 = As[cur][kk + tig + 4][mr];
                float r3 = As[cur][kk + tig + 4][mr + 8];
                ahi[mf][0] = to_tf32(r0); alo[mf][0] = r0 - ahi[mf][0];
                ahi[mf][1] = to_tf32(r1); alo[mf][1] = r1 - ahi[mf][1];
                ahi[mf][2] = to_tf32(r2); alo[mf][2] = r2 - ahi[mf][2];
                ahi[mf][3] = to_tf32(r3); alo[mf][3] = r3 - ahi[mf][3];
            }
#pragma unroll
            for (int nf = 0; nf < 4; ++nf) {
                const int nc = wn * 32 + nf * 8 + g;
                float r0 = Bs[cur][kk + tig    ][nc];
                float r1 = Bs[cur][kk + tig + 4][nc];
                bhi[nf][0] = to_tf32(r0); blo[nf][0] = r0 - bhi[nf][0];
                bhi[nf][1] = to_tf32(r1); blo[nf][1] = r1 - bhi[nf][1];
            }
#pragma unroll
            for (int mf = 0; mf < 2; ++mf)
#pragma unroll
                for (int nf = 0; nf < 4; ++nf)
                    mma_tf32(acc[mf][nf], ahi[mf], bhi[nf]);
#pragma unroll
            for (int mf = 0; mf < 2; ++mf)
#pragma unroll
                for (int nf = 0; nf < 4; ++nf)
                    mma_tf32(acc[mf][nf], alo[mf], bhi[nf]);
#pragma unroll
            for (int mf = 0; mf < 2; ++mf)
#pragma unroll
                for (int nf = 0; nf < 4; ++nf)
                    mma_tf32(acc[mf][nf], ahi[mf], blo[nf]);
        }
        if (s + 1 < S) {
            const int nx = cur ^ 1;
            As[nx][ak + 0][ar] = av.x; As[nx][ak + 1][ar] = av.y;
            As[nx][ak + 2][ar] = av.z; As[nx][ak + 3][ar] = av.w;
            Bs[nx][kc + 0][nl] = b0.x; Bs[nx][kc + 1][nl] = b0.y;
            Bs[nx][kc + 2][nl] = b0.z; Bs[nx][kc + 3][nl] = b0.w;
            Bs[nx][kc + 0][nl + 64] = b1.x; Bs[nx][kc + 1][nl + 64] = b1.y;
            Bs[nx][kc + 2][nl + 64] = b1.z; Bs[nx][kc + 3][nl + 64] = b1.w;
            __syncthreads();
        }
    }

    const float inv_sqrt_emb = 0.04419417382415922f;
    const int mbase = bm + wm * 32;
    const int nbase = bn + wn * 32;
#pragma unroll
    for (int mf = 0; mf < 2; ++mf) {
#pragma unroll
        for (int nf = 0; nf < 4; ++nf) {
#pragma unroll
            for (int t = 0; t < 4; ++t) {
                const int r = mbase + mf * 16 + g + ((t >> 1) << 3);
                const int c = nbase + nf * 8 + 2 * tig + (t & 1);
                if (r < POMO && c < PROB) {
                    const size_t off = ((size_t)b * POMO + r) * PROB + c;
                    out[off] = 10.f * tanhf(acc[mf][nf][t] * inv_sqrt_emb) + mask[off];
                }
            }
        }
    }
}

// ---------------------------------------------------------------------------
// Attention, flash-style (round-3 scalar form — fastest measured).
// ---------------------------------------------------------------------------
__global__ __launch_bounds__(256, 2) void attn_kernel(
    const float* __restrict__ Q, const float* __restrict__ Kb,
    const float* __restrict__ Vb, const float* __restrict__ mask,
    float* __restrict__ O)
{
    extern __shared__ float sma[];
    float* sK = sma;
    float* sV = sma + NNODE * HD;

    const int b = blockIdx.x >> 4;
    const int h = blockIdx.x & 15;
    const float* Kp = Kb + (size_t)b * NNODE * EMB + h * HD;
    const float* Vp = Vb + (size_t)b * NNODE * EMB + h * HD;

    for (int idx = threadIdx.x; idx < NNODE * 8; idx += 256) {
        int n  = idx >> 3;
        int d4 = (idx & 7) << 2;
        *(float4*)(sK + n * HD + d4) = *(const float4*)(Kp + (size_t)n * EMB + d4);
        *(float4*)(sV + n * HD + d4) = *(const float4*)(Vp + (size_t)n * EMB + d4);
    }
    __syncthreads();

    const int n = threadIdx.x;
    if (n >= POMO) return;

    float q[HD];
    const float* Qp = Q + (size_t)(b * POMO + n) * EMB + h * HD;
#pragma unroll
    for (int d4 = 0; d4 < 8; ++d4) {
        float4 t = *(const float4*)(Qp + (d4 << 2));
        q[d4 * 4 + 0] = t.x; q[d4 * 4 + 1] = t.y;
        q[d4 * 4 + 2] = t.z; q[d4 * 4 + 3] = t.w;
    }

    const float* mrow = mask + (size_t)(b * POMO + n) * PROB;
    const float scale = 0.17677669529663687f;

    float mx = -1e30f, l = 0.f;
    float acc[HD];
#pragma unroll
    for (int d = 0; d < HD; ++d) acc[d] = 0.f;

    for (int m = 0; m < NNODE; ++m) {
        const float4* kr4 = (const float4*)(sK + m * HD);
        float s = 0.f;
#pragma unroll
        for (int d4 = 0; d4 < 8; ++d4) {
            float4 kv = kr4[d4];
            s = fmaf(q[d4 * 4 + 0], kv.x, s);
            s = fmaf(q[d4 * 4 + 1], kv.y, s);
            s = fmaf(q[d4 * 4 + 2], kv.z, s);
            s = fmaf(q[d4 * 4 + 3], kv.w, s);
        }
        s *= scale;
        if (m < PROB) s += mrow[m];

        if (s > mx) {
            float sc = __expf(mx - s);
            l *= sc;
#pragma unroll
            for (int d = 0; d < HD; ++d) acc[d] *= sc;
            mx = s;
        }
        float p = __expf(s - mx);
        l += p;
        const float4* vr4 = (const float4*)(sV + m * HD);
#pragma unroll
        for (int d4 = 0; d4 < 8; ++d4) {
            float4 vv = vr4[d4];
            acc[d4 * 4 + 0] = fmaf(p, vv.x, acc[d4 * 4 + 0]);
            acc[d4 * 4 + 1] = fmaf(p, vv.y, acc[d4 * 4 + 1]);
            acc[d4 * 4 + 2] = fmaf(p, vv.z, acc[d4 * 4 + 2]);
            acc[d4 * 4 + 3] = fmaf(p, vv.w, acc[d4 * 4 + 3]);
        }
    }

    float inv = 1.f / l;
    float* Op = O + (size_t)(b * POMO + n) * EMB + h * HD;
#pragma unroll
    for (int d4 = 0; d4 < 8; ++d4) {
        float4 t;
        t.x = acc[d4 * 4 + 0] * inv;
        t.y = acc[d4 * 4 + 1] * inv;
        t.z = acc[d4 * 4 + 2] * inv;
        t.w = acc[d4 * 4 + 3] * inv;
        *(float4*)(Op + (d4 << 2)) = t;
    }
}

// ---------------------------------------------------------------------------
// In-place row softmax over 200 columns, one warp per row.
// ---------------------------------------------------------------------------
__global__ __launch_bounds__(256) void softmax_kernel(float* __restrict__ out)
{
    const int row  = blockIdx.x * 8 + (threadIdx.x >> 5);
    const int lane = threadIdx.x & 31;
    float* p = out + (size_t)row * PROB;

    float v[7];
    float mx = -1e30f;
#pragma unroll
    for (int i = 0; i < 7; ++i) {
        int c = lane + (i << 5);
        v[i] = (c < PROB) ? p[c] : -1e30f;
        mx = fmaxf(mx, v[i]);
    }
#pragma unroll
    for (int off = 16; off; off >>= 1)
        mx = fmaxf(mx, __shfl_xor_sync(0xffffffffu, mx, off));

    float sum = 0.f;
#pragma unroll
    for (int i = 0; i < 7; ++i) { v[i] = __expf(v[i] - mx); sum += v[i]; }
#pragma unroll
    for (int off = 16; off; off >>= 1)
        sum += __shfl_xor_sync(0xffffffffu, sum, off);

    float inv = 1.f / sum;
#pragma unroll
    for (int i = 0; i < 7; ++i) {
        int c = lane + (i << 5);
        if (c < PROB) p[c] = v[i] * inv;
    }
}

// ---------------------------------------------------------------------------
// Launch
// ---------------------------------------------------------------------------
extern "C" void kernel_launch(void* const* d_in, const int* in_sizes, int n_in,
                              void* d_out, int out_size)
{
    const float* nodes = (const float*)d_in[0];
    const float* q1    = (const float*)d_in[1];
    const float* lastn = (const float*)d_in[2];
    const float* mask  = (const float*)d_in[3];
    const float* Wqf   = (const float*)d_in[4];
    const float* Wql   = (const float*)d_in[5];
    const float* Wk    = (const float*)d_in[6];
    const float* Wv    = (const float*)d_in[7];
    const float* Wc    = (const float*)d_in[8];
    const float* bc    = (const float*)d_in[9];
    float* out = (float*)d_out;

    float *Kb, *Vb, *Qb, *Ob, *MHb;
    cudaGetSymbolAddress((void**)&Kb,  g_K);
    cudaGetSymbolAddress((void**)&Vb,  g_V);
    cudaGetSymbolAddress((void**)&Qb,  g_Q);
    cudaGetSymbolAddress((void**)&Ob,  g_O);
    cudaGetSymbolAddress((void**)&MHb, g_MH);

    const int gemm_smem = (ST * ASTG + ST * BSTG) * (int)sizeof(float); // 75776
    cudaFuncSetAttribute(gemm3x,
                         cudaFuncAttributeMaxDynamicSharedMemorySize, gemm_smem);
    const int attn_smem = NNODE * HD * 2 * (int)sizeof(float);          // 51456
    cudaFuncSetAttribute(attn_kernel,
                         cudaFuncAttributeMaxDynamicSharedMemorySize, attn_smem);

    dim3 gKV(EMB / 128, (BB * NNODE + 127) / 128);  // 4 x 101
    gemm3x<<<gKV, 256, gemm_smem>>>(nodes, Wk, nullptr, nullptr, nullptr, Kb,
                                    BB * NNODE, EMB, EMB);
    gemm3x<<<gKV, 256, gemm_smem>>>(nodes, Wv, nullptr, nullptr, nullptr, Vb,
                                    BB * NNODE, EMB, EMB);

    dim3 gQ(EMB / 128, (BB * POMO) / 128);          // 4 x 100
    gemm3x<<<gQ, 256, gemm_smem>>>(q1, Wqf, lastn, Wql, nullptr, Qb,
                                   BB * POMO, EMB, EMB);

    attn_kernel<<<BB * NH, 256, attn_smem>>>(Qb, Kb, Vb, mask, Ob);

    gemm3x<<<gQ, 256, gemm_smem>>>(Ob, Wc, nullptr, nullptr, bc, MHb,
                                   BB * POMO, EMB, EMB);

    dim3 gS(2, 4, BB);
    score2_tf32<<<gS, 256>>>(MHb, nodes, mask, out);

    softmax_kernel<<<(BB * POMO) / 8, 256>>>(out);
}

// round 7
// speedup vs baseline: 1.6762x; 1.2383x over previous
#include <cuda_runtime.h>
#include <cuda_bf16.h>
#include <math.h>

#define BB    64
#define POMO  200
#define PROB  200
#define NNODE 201
#define EMB   512
#define NH    16
#define HD    32

// ---------------------------------------------------------------------------
// Scratch
// ---------------------------------------------------------------------------
__device__ float g_K [BB * NNODE * EMB];
__device__ float g_V [BB * NNODE * EMB];
__device__ float g_Q [BB * POMO  * EMB];

// bf16 hi/lo split operands
__device__ __nv_bfloat16 g_nh [BB * NNODE * EMB], g_nl [BB * NNODE * EMB];  // nodes
__device__ __nv_bfloat16 g_q1h[BB * POMO  * EMB], g_q1l[BB * POMO  * EMB];
__device__ __nv_bfloat16 g_lnh[BB * POMO  * EMB], g_lnl[BB * POMO  * EMB];
__device__ __nv_bfloat16 g_Oh [BB * POMO  * EMB], g_Ol [BB * POMO  * EMB];  // attn out
__device__ __nv_bfloat16 g_MHh[BB * POMO  * EMB], g_MHl[BB * POMO  * EMB];  // mh out
// transposed weights [n][k]
__device__ __nv_bfloat16 g_Wkh [EMB * EMB], g_Wkl [EMB * EMB];
__device__ __nv_bfloat16 g_Wvh [EMB * EMB], g_Wvl [EMB * EMB];
__device__ __nv_bfloat16 g_Wqfh[EMB * EMB], g_Wqfl[EMB * EMB];
__device__ __nv_bfloat16 g_Wqlh[EMB * EMB], g_Wqll[EMB * EMB];
__device__ __nv_bfloat16 g_Wch [EMB * EMB], g_Wcl [EMB * EMB];

// ---------------------------------------------------------------------------
// Helpers
// ---------------------------------------------------------------------------
__device__ __forceinline__ unsigned smem_u32(const void* p) {
    return (unsigned)__cvta_generic_to_shared(p);
}
__device__ __forceinline__ void cp16(unsigned d, const void* s) {
    asm volatile("cp.async.cg.shared.global [%0], [%1], 16;" :: "r"(d), "l"(s));
}
#define CP_COMMIT() asm volatile("cp.async.commit_group;")
#define CP_WAIT1()  asm volatile("cp.async.wait_group 1;")

__device__ __forceinline__ void mma_bf16(float* c, const unsigned* a, const unsigned* b) {
    asm volatile(
        "mma.sync.aligned.m16n8k16.row.col.f32.bf16.bf16.f32 "
        "{%0,%1,%2,%3}, {%4,%5,%6,%7}, {%8,%9}, {%0,%1,%2,%3};\n"
        : "+f"(c[0]), "+f"(c[1]), "+f"(c[2]), "+f"(c[3])
        : "r"(a[0]), "r"(a[1]), "r"(a[2]), "r"(a[3]), "r"(b[0]), "r"(b[1]));
}

__device__ __forceinline__ void split2(float x, __nv_bfloat16& h, __nv_bfloat16& l) {
    h = __float2bfloat16_rn(x);
    l = __float2bfloat16_rn(x - __bfloat162float(h));
}

// ---------------------------------------------------------------------------
// Straight split-convert: X fp32 [n] -> H,L bf16 (n % 4 == 0)
// ---------------------------------------------------------------------------
__global__ __launch_bounds__(256) void convsplit(
    const float* __restrict__ X, __nv_bfloat16* __restrict__ H,
    __nv_bfloat16* __restrict__ L, int n)
{
    int i = (blockIdx.x * 256 + threadIdx.x) * 4;
    if (i >= n) return;
    float4 v = *(const float4*)(X + i);
    __nv_bfloat16 h0, l0, h1, l1, h2, l2, h3, l3;
    split2(v.x, h0, l0); split2(v.y, h1, l1);
    split2(v.z, h2, l2); split2(v.w, h3, l3);
    *(__nv_bfloat162*)(H + i)     = __nv_bfloat162(h0, h1);
    *(__nv_bfloat162*)(H + i + 2) = __nv_bfloat162(h2, h3);
    *(__nv_bfloat162*)(L + i)     = __nv_bfloat162(l0, l1);
    *(__nv_bfloat162*)(L + i + 2) = __nv_bfloat162(l2, l3);
}

// ---------------------------------------------------------------------------
// Transpose + split: W[512][512] fp32 (k-major) -> T[512][512] bf16 [n][k]
// ---------------------------------------------------------------------------
__global__ __launch_bounds__(256) void transconv512(
    const float* __restrict__ W, __nv_bfloat16* __restrict__ Th,
    __nv_bfloat16* __restrict__ Tl)
{
    __shared__ float t[32][33];
    const int tx = threadIdx.x, ty = threadIdx.y;   // (32, 8)
    const int x = blockIdx.x * 32 + tx;             // n
    const int y = blockIdx.y * 32;                  // k base
#pragma unroll
    for (int i = 0; i < 32; i += 8)
        t[ty + i][tx] = W[(size_t)(y + ty + i) * EMB + x];
    __syncthreads();
    const int xo = blockIdx.y * 32 + tx;            // k
    const int yo = blockIdx.x * 32;                 // n base
#pragma unroll
    for (int i = 0; i < 32; i += 8) {
        float v = t[tx][ty + i];
        __nv_bfloat16 h, l;
        split2(v, h, l);
        size_t o = (size_t)(yo + ty + i) * EMB + xo;
        Th[o] = h; Tl[o] = l;
    }
}

// ---------------------------------------------------------------------------
// bf16x3 pipelined GEMM: C = A@B^T_layout (+A2@B2) (+bias)
// A,A2: [M][K] bf16 hi/lo.  B,B2: [N][K] bf16 hi/lo (k-contig both).
// BM=BN=128, BK=16, 3-stage cp.async, 256 thr, warp tile 64x32.
// Optional fp32 C and/or bf16 split outputs Ch/Cl.
// ---------------------------------------------------------------------------
#define GST 3
#define KP  12                 // b32 pitch per row (8 used + 4 pad, conflict-free)
#define ATI (128 * KP)         // b32 per stage per array

__global__ __launch_bounds__(256, 1) void gemm_bf16x3(
    const __nv_bfloat16* __restrict__ Ah,  const __nv_bfloat16* __restrict__ Al,
    const __nv_bfloat16* __restrict__ Bh,  const __nv_bfloat16* __restrict__ Bl,
    const __nv_bfloat16* __restrict__ A2h, const __nv_bfloat16* __restrict__ A2l,
    const __nv_bfloat16* __restrict__ B2h, const __nv_bfloat16* __restrict__ B2l,
    const float* __restrict__ bias, float* __restrict__ C,
    __nv_bfloat16* __restrict__ Ch, __nv_bfloat16* __restrict__ Cl,
    int M, int N, int K)
{
    extern __shared__ unsigned smu[];
    unsigned* sAh = smu;
    unsigned* sAl = smu + GST * ATI;
    unsigned* sBh = smu + 2 * GST * ATI;
    unsigned* sBl = smu + 3 * GST * ATI;

    const int tid  = threadIdx.x;
    const int lane = tid & 31, warp = tid >> 5;
    const int g    = lane >> 2, tig = lane & 3;
    const int wm   = warp >> 2, wn  = warp & 3;
    const int bm   = blockIdx.y * 128, bn = blockIdx.x * 128;

    const int SK = K / 16;
    const int S  = A2h ? 2 * SK : SK;

    const int r    = tid >> 1;      // 0..127
    const int half = tid & 1;       // 16B half of the 32B row

    auto load_tile = [&](int st, int t) {
        const __nv_bfloat16 *pAh, *pAl, *pBh, *pBl; int k0;
        if (t >= SK) { pAh = A2h; pAl = A2l; pBh = B2h; pBl = B2l; k0 = (t - SK) << 4; }
        else         { pAh = Ah;  pAl = Al;  pBh = Bh;  pBl = Bl;  k0 = t << 4; }
        int gr = bm + r; if (gr >= M) gr = M - 1;
        const int gn = bn + r;
        const unsigned off = st * ATI + r * KP + half * 4;
        const size_t ga = (size_t)gr * K + k0 + half * 8;
        const size_t gb = (size_t)gn * K + k0 + half * 8;
        cp16(smem_u32(sAh + off), pAh + ga);
        cp16(smem_u32(sAl + off), pAl + ga);
        cp16(smem_u32(sBh + off), pBh + gb);
        cp16(smem_u32(sBl + off), pBl + gb);
    };

    float acc[4][4][4];
#pragma unroll
    for (int i = 0; i < 4; ++i)
#pragma unroll
        for (int j = 0; j < 4; ++j)
#pragma unroll
            for (int t = 0; t < 4; ++t) acc[i][j][t] = 0.f;

#pragma unroll
    for (int t = 0; t < GST - 1; ++t) {
        if (t < S) load_tile(t, t);
        CP_COMMIT();
    }

    for (int s = 0; s < S; ++s) {
        CP_WAIT1();
        __syncthreads();
        const int nt = s + GST - 1;
        if (nt < S) load_tile(nt % GST, nt);
        CP_COMMIT();

        const unsigned st = (s % GST) * ATI;
        const unsigned* As_ = sAh + st;
        const unsigned* Al_ = sAl + st;
        const unsigned* Bs_ = sBh + st;
        const unsigned* Bl_ = sBl + st;

        unsigned ah[4][4], bh[4][2];
#pragma unroll
        for (int mf = 0; mf < 4; ++mf) {
            const int mr = wm * 64 + mf * 16 + g;
            ah[mf][0] = As_[mr * KP + tig];
            ah[mf][1] = As_[(mr + 8) * KP + tig];
            ah[mf][2] = As_[mr * KP + tig + 4];
            ah[mf][3] = As_[(mr + 8) * KP + tig + 4];
        }
#pragma unroll
        for (int nf = 0; nf < 4; ++nf) {
            const int nc = wn * 32 + nf * 8 + g;
            bh[nf][0] = Bs_[nc * KP + tig];
            bh[nf][1] = Bs_[nc * KP + tig + 4];
        }
#pragma unroll
        for (int mf = 0; mf < 4; ++mf)
#pragma unroll
            for (int nf = 0; nf < 4; ++nf)
                mma_bf16(acc[mf][nf], ah[mf], bh[nf]);

        unsigned al[4][4];
#pragma unroll
        for (int mf = 0; mf < 4; ++mf) {
            const int mr = wm * 64 + mf * 16 + g;
            al[mf][0] = Al_[mr * KP + tig];
            al[mf][1] = Al_[(mr + 8) * KP + tig];
            al[mf][2] = Al_[mr * KP + tig + 4];
            al[mf][3] = Al_[(mr + 8) * KP + tig + 4];
        }
#pragma unroll
        for (int mf = 0; mf < 4; ++mf)
#pragma unroll
            for (int nf = 0; nf < 4; ++nf)
                mma_bf16(acc[mf][nf], al[mf], bh[nf]);

        unsigned bl[4][2];
#pragma unroll
        for (int nf = 0; nf < 4; ++nf) {
            const int nc = wn * 32 + nf * 8 + g;
            bl[nf][0] = Bl_[nc * KP + tig];
            bl[nf][1] = Bl_[nc * KP + tig + 4];
        }
#pragma unroll
        for (int mf = 0; mf < 4; ++mf)
#pragma unroll
            for (int nf = 0; nf < 4; ++nf)
                mma_bf16(acc[mf][nf], ah[mf], bl[nf]);
    }

    // epilogue
#pragma unroll
    for (int nf = 0; nf < 4; ++nf) {
        const int c0 = bn + wn * 32 + nf * 8 + 2 * tig;
        float bb0 = 0.f, bb1 = 0.f;
        if (bias) { bb0 = bias[c0]; bb1 = bias[c0 + 1]; }
#pragma unroll
        for (int mf = 0; mf < 4; ++mf) {
#pragma unroll
            for (int half8 = 0; half8 < 2; ++half8) {
                const int r0 = bm + wm * 64 + mf * 16 + g + half8 * 8;
                if (r0 >= M) continue;
                const float v0 = acc[mf][nf][2 * half8 + 0] + bb0;
                const float v1 = acc[mf][nf][2 * half8 + 1] + bb1;
                if (C) {
                    float2 v; v.x = v0; v.y = v1;
                    *(float2*)(C + (size_t)r0 * N + c0) = v;
                }
                if (Ch) {
                    __nv_bfloat16 h0, l0, h1, l1;
                    split2(v0, h0, l0); split2(v1, h1, l1);
                    *(__nv_bfloat162*)(Ch + (size_t)r0 * N + c0) = __nv_bfloat162(h0, h1);
                    *(__nv_bfloat162*)(Cl + (size_t)r0 * N + c0) = __nv_bfloat162(l0, l1);
                }
            }
        }
    }
}

// ---------------------------------------------------------------------------
// score2 bf16x3: per-batch NT GEMM MH[200,512] @ nodes[:200,512]^T with
// /sqrt(EMB) -> 10*tanh -> +mask epilogue. BM=64, BN=128.
// ---------------------------------------------------------------------------
#define S_ATI (64 * KP)
#define S_BTI (128 * KP)

__global__ __launch_bounds__(256, 2) void score2_bf16(
    const __nv_bfloat16* __restrict__ MHh, const __nv_bfloat16* __restrict__ MHl,
    const __nv_bfloat16* __restrict__ Nh,  const __nv_bfloat16* __restrict__ Nl,
    const float* __restrict__ mask, float* __restrict__ out)
{
    extern __shared__ unsigned smu[];
    unsigned* sAh = smu;
    unsigned* sAl = smu + GST * S_ATI;
    unsigned* sBh = smu + 2 * GST * S_ATI;
    unsigned* sBl = smu + 2 * GST * S_ATI + GST * S_BTI;

    const int tid  = threadIdx.x;
    const int lane = tid & 31, warp = tid >> 5;
    const int g    = lane >> 2, tig = lane & 3;
    const int wm   = warp >> 2, wn  = warp & 3;
    const int b    = blockIdx.z;
    const int bm   = blockIdx.y * 64, bn = blockIdx.x * 128;

    const int rb = tid >> 1, half = tid & 1;   // B rows 0..127
    const int ra = (tid & 127) >> 1;           // A rows 0..63 (tid<128)

    auto load_tile = [&](int st, int t) {
        const int k0 = t << 4;
        int gb = bn + rb; if (gb >= PROB) gb = PROB - 1;
        const size_t go = ((size_t)b * NNODE + gb) * EMB + k0 + half * 8;
        const unsigned ob = st * S_BTI + rb * KP + half * 4;
        cp16(smem_u32(sBh + ob), Nh + go);
        cp16(smem_u32(sBl + ob), Nl + go);
        if (tid < 128) {
            int ga = bm + ra; if (ga >= POMO) ga = POMO - 1;
            const size_t ao = ((size_t)b * POMO + ga) * EMB + k0 + half * 8;
            const unsigned oa = st * S_ATI + ra * KP + half * 4;
            cp16(smem_u32(sAh + oa), MHh + ao);
            cp16(smem_u32(sAl + oa), MHl + ao);
        }
    };

    float acc[2][4][4];
#pragma unroll
    for (int i = 0; i < 2; ++i)
#pragma unroll
        for (int j = 0; j < 4; ++j)
#pragma unroll
            for (int t = 0; t < 4; ++t) acc[i][j][t] = 0.f;

    const int S = EMB / 16;
#pragma unroll
    for (int t = 0; t < GST - 1; ++t) {
        if (t < S) load_tile(t, t);
        CP_COMMIT();
    }

    for (int s = 0; s < S; ++s) {
        CP_WAIT1();
        __syncthreads();
        const int nt = s + GST - 1;
        if (nt < S) load_tile(nt % GST, nt);
        CP_COMMIT();

        const unsigned* As_ = sAh + (s % GST) * S_ATI;
        const unsigned* Al_ = sAl + (s % GST) * S_ATI;
        const unsigned* Bs_ = sBh + (s % GST) * S_BTI;
        const unsigned* Bl_ = sBl + (s % GST) * S_BTI;

        unsigned ah[2][4], bh[4][2];
#pragma unroll
        for (int mf = 0; mf < 2; ++mf) {
            const int mr = wm * 32 + mf * 16 + g;
            ah[mf][0] = As_[mr * KP + tig];
            ah[mf][1] = As_[(mr + 8) * KP + tig];
            ah[mf][2] = As_[mr * KP + tig + 4];
            ah[mf][3] = As_[(mr + 8) * KP + tig + 4];
        }
#pragma unroll
        for (int nf = 0; nf < 4; ++nf) {
            const int nc = wn * 32 + nf * 8 + g;
            bh[nf][0] = Bs_[nc * KP + tig];
            bh[nf][1] = Bs_[nc * KP + tig + 4];
        }
#pragma unroll
        for (int mf = 0; mf < 2; ++mf)
#pragma unroll
            for (int nf = 0; nf < 4; ++nf)
                mma_bf16(acc[mf][nf], ah[mf], bh[nf]);

        unsigned al[2][4];
#pragma unroll
        for (int mf = 0; mf < 2; ++mf) {
            const int mr = wm * 32 + mf * 16 + g;
            al[mf][0] = Al_[mr * KP + tig];
            al[mf][1] = Al_[(mr + 8) * KP + tig];
            al[mf][2] = Al_[mr * KP + tig + 4];
            al[mf][3] = Al_[(mr + 8) * KP + tig + 4];
        }
#pragma unroll
        for (int mf = 0; mf < 2; ++mf)
#pragma unroll
            for (int nf = 0; nf < 4; ++nf)
                mma_bf16(acc[mf][nf], al[mf], bh[nf]);

        unsigned bl[4][2];
#pragma unroll
        for (int nf = 0; nf < 4; ++nf) {
            const int nc = wn * 32 + nf * 8 + g;
            bl[nf][0] = Bl_[nc * KP + tig];
            bl[nf][1] = Bl_[nc * KP + tig + 4];
        }
#pragma unroll
        for (int mf = 0; mf < 2; ++mf)
#pragma unroll
            for (int nf = 0; nf < 4; ++nf)
                mma_bf16(acc[mf][nf], ah[mf], bl[nf]);
    }

    const float inv_sqrt_emb = 0.04419417382415922f;
#pragma unroll
    for (int mf = 0; mf < 2; ++mf) {
#pragma unroll
        for (int nf = 0; nf < 4; ++nf) {
#pragma unroll
            for (int t = 0; t < 4; ++t) {
                const int r = bm + wm * 32 + mf * 16 + g + ((t >> 1) << 3);
                const int c = bn + wn * 32 + nf * 8 + 2 * tig + (t & 1);
                if (r < POMO && c < PROB) {
                    const size_t off = ((size_t)b * POMO + r) * PROB + c;
                    out[off] = 10.f * tanhf(acc[mf][nf][t] * inv_sqrt_emb) + mask[off];
                }
            }
        }
    }
}

// ---------------------------------------------------------------------------
// Attention, flash-style; epilogue emits bf16 hi/lo for the Wc GEMM.
// ---------------------------------------------------------------------------
__global__ __launch_bounds__(256, 2) void attn_kernel(
    const float* __restrict__ Q, const float* __restrict__ Kb,
    const float* __restrict__ Vb, const float* __restrict__ mask,
    __nv_bfloat16* __restrict__ Oh, __nv_bfloat16* __restrict__ Ol)
{
    extern __shared__ float sma[];
    float* sK = sma;
    float* sV = sma + NNODE * HD;

    const int b  = blockIdx.x >> 4;
    const int hh = blockIdx.x & 15;
    const float* Kp = Kb + (size_t)b * NNODE * EMB + hh * HD;
    const float* Vp = Vb + (size_t)b * NNODE * EMB + hh * HD;

    for (int idx = threadIdx.x; idx < NNODE * 8; idx += 256) {
        int n  = idx >> 3;
        int d4 = (idx & 7) << 2;
        *(float4*)(sK + n * HD + d4) = *(const float4*)(Kp + (size_t)n * EMB + d4);
        *(float4*)(sV + n * HD + d4) = *(const float4*)(Vp + (size_t)n * EMB + d4);
    }
    __syncthreads();

    const int n = threadIdx.x;
    if (n >= POMO) return;

    float q[HD];
    const float* Qp = Q + (size_t)(b * POMO + n) * EMB + hh * HD;
#pragma unroll
    for (int d4 = 0; d4 < 8; ++d4) {
        float4 t = *(const float4*)(Qp + (d4 << 2));
        q[d4 * 4 + 0] = t.x; q[d4 * 4 + 1] = t.y;
        q[d4 * 4 + 2] = t.z; q[d4 * 4 + 3] = t.w;
    }

    const float* mrow = mask + (size_t)(b * POMO + n) * PROB;
    const float scale = 0.17677669529663687f;

    float mx = -1e30f, l = 0.f;
    float acc[HD];
#pragma unroll
    for (int d = 0; d < HD; ++d) acc[d] = 0.f;

    for (int m = 0; m < NNODE; ++m) {
        const float4* kr4 = (const float4*)(sK + m * HD);
        float s = 0.f;
#pragma unroll
        for (int d4 = 0; d4 < 8; ++d4) {
            float4 kv = kr4[d4];
            s = fmaf(q[d4 * 4 + 0], kv.x, s);
            s = fmaf(q[d4 * 4 + 1], kv.y, s);
            s = fmaf(q[d4 * 4 + 2], kv.z, s);
            s = fmaf(q[d4 * 4 + 3], kv.w, s);
        }
        s *= scale;
        if (m < PROB) s += mrow[m];

        if (s > mx) {
            float sc = __expf(mx - s);
            l *= sc;
#pragma unroll
            for (int d = 0; d < HD; ++d) acc[d] *= sc;
            mx = s;
        }
        float p = __expf(s - mx);
        l += p;
        const float4* vr4 = (const float4*)(sV + m * HD);
#pragma unroll
        for (int d4 = 0; d4 < 8; ++d4) {
            float4 vv = vr4[d4];
            acc[d4 * 4 + 0] = fmaf(p, vv.x, acc[d4 * 4 + 0]);
            acc[d4 * 4 + 1] = fmaf(p, vv.y, acc[d4 * 4 + 1]);
            acc[d4 * 4 + 2] = fmaf(p, vv.z, acc[d4 * 4 + 2]);
            acc[d4 * 4 + 3] = fmaf(p, vv.w, acc[d4 * 4 + 3]);
        }
    }

    const float inv = 1.f / l;
    const size_t base = (size_t)(b * POMO + n) * EMB + hh * HD;
#pragma unroll
    for (int d4 = 0; d4 < 8; ++d4) {
        float v0 = acc[d4 * 4 + 0] * inv, v1 = acc[d4 * 4 + 1] * inv;
        float v2 = acc[d4 * 4 + 2] * inv, v3 = acc[d4 * 4 + 3] * inv;
        __nv_bfloat16 h0, l0, h1, l1, h2, l2, h3, l3;
        split2(v0, h0, l0); split2(v1, h1, l1);
        split2(v2, h2, l2); split2(v3, h3, l3);
        *(__nv_bfloat162*)(Oh + base + (d4 << 2))     = __nv_bfloat162(h0, h1);
        *(__nv_bfloat162*)(Oh + base + (d4 << 2) + 2) = __nv_bfloat162(h2, h3);
        *(__nv_bfloat162*)(Ol + base + (d4 << 2))     = __nv_bfloat162(l0, l1);
        *(__nv_bfloat162*)(Ol + base + (d4 << 2) + 2) = __nv_bfloat162(l2, l3);
    }
}

// ---------------------------------------------------------------------------
// In-place row softmax over 200 columns, one warp per row.
// ---------------------------------------------------------------------------
__global__ __launch_bounds__(256) void softmax_kernel(float* __restrict__ out)
{
    const int row  = blockIdx.x * 8 + (threadIdx.x >> 5);
    const int lane = threadIdx.x & 31;
    float* p = out + (size_t)row * PROB;

    float v[7];
    float mx = -1e30f;
#pragma unroll
    for (int i = 0; i < 7; ++i) {
        int c = lane + (i << 5);
        v[i] = (c < PROB) ? p[c] : -1e30f;
        mx = fmaxf(mx, v[i]);
    }
#pragma unroll
    for (int off = 16; off; off >>= 1)
        mx = fmaxf(mx, __shfl_xor_sync(0xffffffffu, mx, off));

    float sum = 0.f;
#pragma unroll
    for (int i = 0; i < 7; ++i) { v[i] = __expf(v[i] - mx); sum += v[i]; }
#pragma unroll
    for (int off = 16; off; off >>= 1)
        sum += __shfl_xor_sync(0xffffffffu, sum, off);

    float inv = 1.f / sum;
#pragma unroll
    for (int i = 0; i < 7; ++i) {
        int c = lane + (i << 5);
        if (c < PROB) p[c] = v[i] * inv;
    }
}

// ---------------------------------------------------------------------------
// Launch
// ---------------------------------------------------------------------------
extern "C" void kernel_launch(void* const* d_in, const int* in_sizes, int n_in,
                              void* d_out, int out_size)
{
    const float* nodes = (const float*)d_in[0];
    const float* q1    = (const float*)d_in[1];
    const float* lastn = (const float*)d_in[2];
    const float* mask  = (const float*)d_in[3];
    const float* Wqf   = (const float*)d_in[4];
    const float* Wql   = (const float*)d_in[5];
    const float* Wk    = (const float*)d_in[6];
    const float* Wv    = (const float*)d_in[7];
    const float* Wc    = (const float*)d_in[8];
    const float* bc    = (const float*)d_in[9];
    float* out = (float*)d_out;

    float *Kb, *Vb, *Qb;
    cudaGetSymbolAddress((void**)&Kb, g_K);
    cudaGetSymbolAddress((void**)&Vb, g_V);
    cudaGetSymbolAddress((void**)&Qb, g_Q);

    __nv_bfloat16 *nh, *nl, *q1h, *q1l, *lnh, *lnl, *Oh, *Ol, *MHh, *MHl;
    __nv_bfloat16 *Wkh, *Wkl, *Wvh, *Wvl, *Wqfh, *Wqfl, *Wqlh, *Wqll, *Wch, *Wcl;
    cudaGetSymbolAddress((void**)&nh,   g_nh);   cudaGetSymbolAddress((void**)&nl,   g_nl);
    cudaGetSymbolAddress((void**)&q1h,  g_q1h);  cudaGetSymbolAddress((void**)&q1l,  g_q1l);
    cudaGetSymbolAddress((void**)&lnh,  g_lnh);  cudaGetSymbolAddress((void**)&lnl,  g_lnl);
    cudaGetSymbolAddress((void**)&Oh,   g_Oh);   cudaGetSymbolAddress((void**)&Ol,   g_Ol);
    cudaGetSymbolAddress((void**)&MHh,  g_MHh);  cudaGetSymbolAddress((void**)&MHl,  g_MHl);
    cudaGetSymbolAddress((void**)&Wkh,  g_Wkh);  cudaGetSymbolAddress((void**)&Wkl,  g_Wkl);
    cudaGetSymbolAddress((void**)&Wvh,  g_Wvh);  cudaGetSymbolAddress((void**)&Wvl,  g_Wvl);
    cudaGetSymbolAddress((void**)&Wqfh, g_Wqfh); cudaGetSymbolAddress((void**)&Wqfl, g_Wqfl);
    cudaGetSymbolAddress((void**)&Wqlh, g_Wqlh); cudaGetSymbolAddress((void**)&Wqll, g_Wqll);
    cudaGetSymbolAddress((void**)&Wch,  g_Wch);  cudaGetSymbolAddress((void**)&Wcl,  g_Wcl);

    const int gemm_smem = 4 * GST * ATI * 4;                       // 73728
    cudaFuncSetAttribute(gemm_bf16x3,
                         cudaFuncAttributeMaxDynamicSharedMemorySize, gemm_smem);
    const int s2_smem = (2 * GST * S_ATI + 2 * GST * S_BTI) * 4;   // 55296
    cudaFuncSetAttribute(score2_bf16,
                         cudaFuncAttributeMaxDynamicSharedMemorySize, s2_smem);
    const int attn_smem = NNODE * HD * 2 * (int)sizeof(float);     // 51456
    cudaFuncSetAttribute(attn_kernel,
                         cudaFuncAttributeMaxDynamicSharedMemorySize, attn_smem);

    // --- split-convert inputs ---
    const int nNodes = BB * NNODE * EMB, nAct = BB * POMO * EMB;
    convsplit<<<(nNodes / 4 + 255) / 256, 256>>>(nodes, nh,  nl,  nNodes);
    convsplit<<<(nAct   / 4 + 255) / 256, 256>>>(q1,    q1h, q1l, nAct);
    convsplit<<<(nAct   / 4 + 255) / 256, 256>>>(lastn, lnh, lnl, nAct);
    dim3 tg(16, 16), tb(32, 8);
    transconv512<<<tg, tb>>>(Wk,  Wkh,  Wkl);
    transconv512<<<tg, tb>>>(Wv,  Wvh,  Wvl);
    transconv512<<<tg, tb>>>(Wqf, Wqfh, Wqfl);
    transconv512<<<tg, tb>>>(Wql, Wqlh, Wqll);
    transconv512<<<tg, tb>>>(Wc,  Wch,  Wcl);

    // --- projections ---
    dim3 gKV(EMB / 128, (BB * NNODE + 127) / 128);  // 4 x 101
    gemm_bf16x3<<<gKV, 256, gemm_smem>>>(nh, nl, Wkh, Wkl,
        nullptr, nullptr, nullptr, nullptr, nullptr, Kb, nullptr, nullptr,
        BB * NNODE, EMB, EMB);
    gemm_bf16x3<<<gKV, 256, gemm_smem>>>(nh, nl, Wvh, Wvl,
        nullptr, nullptr, nullptr, nullptr, nullptr, Vb, nullptr, nullptr,
        BB * NNODE, EMB, EMB);

    dim3 gQ(EMB / 128, (BB * POMO) / 128);          // 4 x 100
    gemm_bf16x3<<<gQ, 256, gemm_smem>>>(q1h, q1l, Wqfh, Wqfl,
        lnh, lnl, Wqlh, Wqll, nullptr, Qb, nullptr, nullptr,
        BB * POMO, EMB, EMB);

    // --- attention ---
    attn_kernel<<<BB * NH, 256, attn_smem>>>(Qb, Kb, Vb, mask, Oh, Ol);

    // --- Wc projection (emit bf16 split for score2) ---
    gemm_bf16x3<<<gQ, 256, gemm_smem>>>(Oh, Ol, Wch, Wcl,
        nullptr, nullptr, nullptr, nullptr, bc, nullptr, MHh, MHl,
        BB * POMO, EMB, EMB);

    // --- score2 + softmax ---
    dim3 gS(2, 4, BB);
    score2_bf16<<<gS, 256, s2_smem>>>(MHh, MHl, nh, nl, mask, out);

    softmax_kernel<<<(BB * POMO) / 8, 256>>>(out);
}

// round 10
// speedup vs baseline: 1.8545x; 1.1064x over previous
#include <cuda_runtime.h>
#include <cuda_bf16.h>
#include <math.h>

#define BB    64
#define POMO  200
#define PROB  200
#define NNODE 201
#define EMB   512
#define NH    16
#define HD    32

// ---------------------------------------------------------------------------
// Scratch
// ---------------------------------------------------------------------------
// bf16 hi/lo split operands
__device__ __nv_bfloat16 g_nh [BB * NNODE * EMB], g_nl [BB * NNODE * EMB];  // nodes
__device__ __nv_bfloat16 g_q1h[BB * POMO  * EMB], g_q1l[BB * POMO  * EMB];
__device__ __nv_bfloat16 g_lnh[BB * POMO  * EMB], g_lnl[BB * POMO  * EMB];
__device__ __nv_bfloat16 g_Kh [BB * NNODE * EMB], g_Kl [BB * NNODE * EMB];  // K proj
__device__ __nv_bfloat16 g_Vh [BB * NNODE * EMB], g_Vl [BB * NNODE * EMB];  // V proj
__device__ __nv_bfloat16 g_Qh [BB * POMO  * EMB], g_Ql [BB * POMO  * EMB];  // Q proj
__device__ __nv_bfloat16 g_Oh [BB * POMO  * EMB], g_Ol [BB * POMO  * EMB];  // attn out
__device__ __nv_bfloat16 g_MHh[BB * POMO  * EMB], g_MHl[BB * POMO  * EMB];  // mh out
// transposed weights [n][k]
__device__ __nv_bfloat16 g_Wkh [EMB * EMB], g_Wkl [EMB * EMB];
__device__ __nv_bfloat16 g_Wvh [EMB * EMB], g_Wvl [EMB * EMB];
__device__ __nv_bfloat16 g_Wqfh[EMB * EMB], g_Wqfl[EMB * EMB];
__device__ __nv_bfloat16 g_Wqlh[EMB * EMB], g_Wqll[EMB * EMB];
__device__ __nv_bfloat16 g_Wch [EMB * EMB], g_Wcl [EMB * EMB];

// ---------------------------------------------------------------------------
// Helpers
// ---------------------------------------------------------------------------
__device__ __forceinline__ unsigned smem_u32(const void* p) {
    return (unsigned)__cvta_generic_to_shared(p);
}
__device__ __forceinline__ void cp16(unsigned d, const void* s) {
    asm volatile("cp.async.cg.shared.global [%0], [%1], 16;" :: "r"(d), "l"(s));
}
#define CP_COMMIT() asm volatile("cp.async.commit_group;")
#define CP_WAIT1()  asm volatile("cp.async.wait_group 1;")
#define CP_WAIT0()  asm volatile("cp.async.wait_group 0;")

__device__ __forceinline__ void mma_bf16(float* c, const unsigned* a, const unsigned* b) {
    asm volatile(
        "mma.sync.aligned.m16n8k16.row.col.f32.bf16.bf16.f32 "
        "{%0,%1,%2,%3}, {%4,%5,%6,%7}, {%8,%9}, {%0,%1,%2,%3};\n"
        : "+f"(c[0]), "+f"(c[1]), "+f"(c[2]), "+f"(c[3])
        : "r"(a[0]), "r"(a[1]), "r"(a[2]), "r"(a[3]), "r"(b[0]), "r"(b[1]));
}

__device__ __forceinline__ void split2(float x, __nv_bfloat16& h, __nv_bfloat16& l) {
    h = __float2bfloat16_rn(x);
    l = __float2bfloat16_rn(x - __bfloat162float(h));
}

// pack (x,y) into bf16x2 hi and lo words (x -> low half)
__device__ __forceinline__ void pks(float x, float y, unsigned& hi, unsigned& lo) {
    __nv_bfloat16 hx = __float2bfloat16_rn(x), hy = __float2bfloat16_rn(y);
    __nv_bfloat16 lx = __float2bfloat16_rn(x - __bfloat162float(hx));
    __nv_bfloat16 ly = __float2bfloat16_rn(y - __bfloat162float(hy));
    __nv_bfloat162 th(hx, hy), tl(lx, ly);
    hi = *reinterpret_cast<unsigned*>(&th);
    lo = *reinterpret_cast<unsigned*>(&tl);
}

// ---------------------------------------------------------------------------
// Straight split-convert: X fp32 [n] -> H,L bf16 (n % 4 == 0)
// ---------------------------------------------------------------------------
__global__ __launch_bounds__(256) void convsplit(
    const float* __restrict__ X, __nv_bfloat16* __restrict__ H,
    __nv_bfloat16* __restrict__ L, int n)
{
    int i = (blockIdx.x * 256 + threadIdx.x) * 4;
    if (i >= n) return;
    float4 v = *(const float4*)(X + i);
    __nv_bfloat16 h0, l0, h1, l1, h2, l2, h3, l3;
    split2(v.x, h0, l0); split2(v.y, h1, l1);
    split2(v.z, h2, l2); split2(v.w, h3, l3);
    *(__nv_bfloat162*)(H + i)     = __nv_bfloat162(h0, h1);
    *(__nv_bfloat162*)(H + i + 2) = __nv_bfloat162(h2, h3);
    *(__nv_bfloat162*)(L + i)     = __nv_bfloat162(l0, l1);
    *(__nv_bfloat162*)(L + i + 2) = __nv_bfloat162(l2, l3);
}

// ---------------------------------------------------------------------------
// Transpose + split: W[512][512] fp32 (k-major) -> T[512][512] bf16 [n][k]
// ---------------------------------------------------------------------------
__global__ __launch_bounds__(256) void transconv512(
    const float* __restrict__ W, __nv_bfloat16* __restrict__ Th,
    __nv_bfloat16* __restrict__ Tl)
{
    __shared__ float t[32][33];
    const int tx = threadIdx.x, ty = threadIdx.y;   // (32, 8)
    const int x = blockIdx.x * 32 + tx;             // n
    const int y = blockIdx.y * 32;                  // k base
#pragma unroll
    for (int i = 0; i < 32; i += 8)
        t[ty + i][tx] = W[(size_t)(y + ty + i) * EMB + x];
    __syncthreads();
    const int xo = blockIdx.y * 32 + tx;            // k
    const int yo = blockIdx.x * 32;                 // n base
#pragma unroll
    for (int i = 0; i < 32; i += 8) {
        float v = t[tx][ty + i];
        __nv_bfloat16 h, l;
        split2(v, h, l);
        size_t o = (size_t)(yo + ty + i) * EMB + xo;
        Th[o] = h; Tl[o] = l;
    }
}

// ---------------------------------------------------------------------------
// bf16x3 pipelined GEMM: C = A@B^T_layout (+A2@B2) (+bias)
// ---------------------------------------------------------------------------
#define GST 3
#define KP  12
#define ATI (128 * KP)

__global__ __launch_bounds__(256, 1) void gemm_bf16x3(
    const __nv_bfloat16* __restrict__ Ah,  const __nv_bfloat16* __restrict__ Al,
    const __nv_bfloat16* __restrict__ Bh,  const __nv_bfloat16* __restrict__ Bl,
    const __nv_bfloat16* __restrict__ A2h, const __nv_bfloat16* __restrict__ A2l,
    const __nv_bfloat16* __restrict__ B2h, const __nv_bfloat16* __restrict__ B2l,
    const float* __restrict__ bias, float* __restrict__ C,
    __nv_bfloat16* __restrict__ Ch, __nv_bfloat16* __restrict__ Cl,
    int M, int N, int K)
{
    extern __shared__ unsigned smu[];
    unsigned* sAh = smu;
    unsigned* sAl = smu + GST * ATI;
    unsigned* sBh = smu + 2 * GST * ATI;
    unsigned* sBl = smu + 3 * GST * ATI;

    const int tid  = threadIdx.x;
    const int lane = tid & 31, warp = tid >> 5;
    const int g    = lane >> 2, tig = lane & 3;
    const int wm   = warp >> 2, wn  = warp & 3;
    const int bm   = blockIdx.y * 128, bn = blockIdx.x * 128;

    const int SK = K / 16;
    const int S  = A2h ? 2 * SK : SK;

    const int r    = tid >> 1;
    const int half = tid & 1;

    auto load_tile = [&](int st, int t) {
        const __nv_bfloat16 *pAh, *pAl, *pBh, *pBl; int k0;
        if (t >= SK) { pAh = A2h; pAl = A2l; pBh = B2h; pBl = B2l; k0 = (t - SK) << 4; }
        else         { pAh = Ah;  pAl = Al;  pBh = Bh;  pBl = Bl;  k0 = t << 4; }
        int gr = bm + r; if (gr >= M) gr = M - 1;
        const int gn = bn + r;
        const unsigned off = st * ATI + r * KP + half * 4;
        const size_t ga = (size_t)gr * K + k0 + half * 8;
        const size_t gb = (size_t)gn * K + k0 + half * 8;
        cp16(smem_u32(sAh + off), pAh + ga);
        cp16(smem_u32(sAl + off), pAl + ga);
        cp16(smem_u32(sBh + off), pBh + gb);
        cp16(smem_u32(sBl + off), pBl + gb);
    };

    float acc[4][4][4];
#pragma unroll
    for (int i = 0; i < 4; ++i)
#pragma unroll
        for (int j = 0; j < 4; ++j)
#pragma unroll
            for (int t = 0; t < 4; ++t) acc[i][j][t] = 0.f;

#pragma unroll
    for (int t = 0; t < GST - 1; ++t) {
        if (t < S) load_tile(t, t);
        CP_COMMIT();
    }

    for (int s = 0; s < S; ++s) {
        CP_WAIT1();
        __syncthreads();
        const int nt = s + GST - 1;
        if (nt < S) load_tile(nt % GST, nt);
        CP_COMMIT();

        const unsigned st = (s % GST) * ATI;
        const unsigned* As_ = sAh + st;
        const unsigned* Al_ = sAl + st;
        const unsigned* Bs_ = sBh + st;
        const unsigned* Bl_ = sBl + st;

        unsigned ah[4][4], bh[4][2];
#pragma unroll
        for (int mf = 0; mf < 4; ++mf) {
            const int mr = wm * 64 + mf * 16 + g;
            ah[mf][0] = As_[mr * KP + tig];
            ah[mf][1] = As_[(mr + 8) * KP + tig];
            ah[mf][2] = As_[mr * KP + tig + 4];
            ah[mf][3] = As_[(mr + 8) * KP + tig + 4];
        }
#pragma unroll
        for (int nf = 0; nf < 4; ++nf) {
            const int nc = wn * 32 + nf * 8 + g;
            bh[nf][0] = Bs_[nc * KP + tig];
            bh[nf][1] = Bs_[nc * KP + tig + 4];
        }
#pragma unroll
        for (int mf = 0; mf < 4; ++mf)
#pragma unroll
            for (int nf = 0; nf < 4; ++nf)
                mma_bf16(acc[mf][nf], ah[mf], bh[nf]);

        unsigned al[4][4];
#pragma unroll
        for (int mf = 0; mf < 4; ++mf) {
            const int mr = wm * 64 + mf * 16 + g;
            al[mf][0] = Al_[mr * KP + tig];
            al[mf][1] = Al_[(mr + 8) * KP + tig];
            al[mf][2] = Al_[mr * KP + tig + 4];
            al[mf][3] = Al_[(mr + 8) * KP + tig + 4];
        }
#pragma unroll
        for (int mf = 0; mf < 4; ++mf)
#pragma unroll
            for (int nf = 0; nf < 4; ++nf)
                mma_bf16(acc[mf][nf], al[mf], bh[nf]);

        unsigned bl[4][2];
#pragma unroll
        for (int nf = 0; nf < 4; ++nf) {
            const int nc = wn * 32 + nf * 8 + g;
            bl[nf][0] = Bl_[nc * KP + tig];
            bl[nf][1] = Bl_[nc * KP + tig + 4];
        }
#pragma unroll
        for (int mf = 0; mf < 4; ++mf)
#pragma unroll
            for (int nf = 0; nf < 4; ++nf)
                mma_bf16(acc[mf][nf], ah[mf], bl[nf]);
    }

#pragma unroll
    for (int nf = 0; nf < 4; ++nf) {
        const int c0 = bn + wn * 32 + nf * 8 + 2 * tig;
        float bb0 = 0.f, bb1 = 0.f;
        if (bias) { bb0 = bias[c0]; bb1 = bias[c0 + 1]; }
#pragma unroll
        for (int mf = 0; mf < 4; ++mf) {
#pragma unroll
            for (int half8 = 0; half8 < 2; ++half8) {
                const int r0 = bm + wm * 64 + mf * 16 + g + half8 * 8;
                if (r0 >= M) continue;
                const float v0 = acc[mf][nf][2 * half8 + 0] + bb0;
                const float v1 = acc[mf][nf][2 * half8 + 1] + bb1;
                if (C) {
                    float2 v; v.x = v0; v.y = v1;
                    *(float2*)(C + (size_t)r0 * N + c0) = v;
                }
                if (Ch) {
                    __nv_bfloat16 h0, l0, h1, l1;
                    split2(v0, h0, l0); split2(v1, h1, l1);
                    *(__nv_bfloat162*)(Ch + (size_t)r0 * N + c0) = __nv_bfloat162(h0, h1);
                    *(__nv_bfloat162*)(Cl + (size_t)r0 * N + c0) = __nv_bfloat162(l0, l1);
                }
            }
        }
    }
}

// ---------------------------------------------------------------------------
// Tensor-core flash attention (fixed: quad-reduce softmax denominator).
// ---------------------------------------------------------------------------
#define AT_KP 20    // K row pitch (u32) = 40 bf16
#define AT_VP 108   // Vt row pitch (u32) = 216 bf16
#define AT_MP 204   // mask row pitch (floats)
#define ATTN_SMEM (2*208*AT_KP*4 + 2*32*AT_VP*4 + 64*AT_MP*4)  // 113152

__global__ __launch_bounds__(128, 2) void attn_mma(
    const __nv_bfloat16* __restrict__ Qh, const __nv_bfloat16* __restrict__ Ql,
    const __nv_bfloat16* __restrict__ Kh, const __nv_bfloat16* __restrict__ Kl,
    const __nv_bfloat16* __restrict__ Vh, const __nv_bfloat16* __restrict__ Vl,
    const float* __restrict__ mask,
    __nv_bfloat16* __restrict__ Oh, __nv_bfloat16* __restrict__ Ol)
{
    extern __shared__ char smc[];
    unsigned* sKh = (unsigned*)smc;             // [208][20] u32
    unsigned* sKl = sKh + 208 * AT_KP;
    unsigned* sVh = sKl + 208 * AT_KP;          // Vt [32][108] u32
    unsigned* sVl = sVh + 32 * AT_VP;
    float*    sMk = (float*)(sVl + 32 * AT_VP); // [64][204] f32

    const int tid = threadIdx.x;
    const int bx = blockIdx.x, h = blockIdx.y, b = blockIdx.z;
    const int lane = tid & 31, w = tid >> 5;
    const int g = lane >> 2, tig = lane & 3;
    const int qbase = bx * 64;

    const unsigned* Khu = (const unsigned*)Kh;
    const unsigned* Klu = (const unsigned*)Kl;

    // K hi/lo: 201 rows x 4 x 16B chunks via cp.async
    for (int i = tid; i < 201 * 4; i += 128) {
        const int row = i >> 2, c = i & 3;
        const size_t src = (((size_t)(b * NNODE + row) * EMB + h * HD) >> 1) + c * 4;
        const unsigned dst = row * AT_KP + c * 4;
        cp16(smem_u32(sKh + dst), Khu + src);
        cp16(smem_u32(sKl + dst), Klu + src);
    }
    // mask block: 64 rows x 50 float4
    for (int i = tid; i < 3200; i += 128) {
        const int r = i / 50, c4 = i % 50;
        int grow = qbase + r; if (grow >= POMO) grow = POMO - 1;
        cp16(smem_u32(sMk + r * AT_MP + c4 * 4),
             mask + (size_t)(b * POMO + grow) * PROB + c4 * 4);
    }
    CP_COMMIT();

    // V transpose (plain loads + scalar STS)
    {
        const __nv_bfloat162* Vh2 = (const __nv_bfloat162*)Vh;
        const __nv_bfloat162* Vl2 = (const __nv_bfloat162*)Vl;
        __nv_bfloat16* pVh = (__nv_bfloat16*)sVh;
        __nv_bfloat16* pVl = (__nv_bfloat16*)sVl;
        for (int i = tid; i < 201 * 16; i += 128) {
            const int row = i >> 4, wd = i & 15;
            const size_t src = (((size_t)(b * NNODE + row) * EMB + h * HD) >> 1) + wd;
            __nv_bfloat162 th = Vh2[src];
            __nv_bfloat162 tl = Vl2[src];
            const int d0 = wd * 2;
            pVh[d0 * 216 + row] = th.x; pVh[(d0 + 1) * 216 + row] = th.y;
            pVl[d0 * 216 + row] = tl.x; pVl[(d0 + 1) * 216 + row] = tl.y;
        }
        // zero pads: K rows 201..207, Vt key-cols 201..207
        for (int i = tid; i < 7 * AT_KP; i += 128) {
            sKh[201 * AT_KP + i] = 0;
            sKl[201 * AT_KP + i] = 0;
        }
        const __nv_bfloat16 z = __float2bfloat16(0.f);
        for (int i = tid; i < 32 * 7; i += 128) {
            const int d = i / 7, c = 201 + i % 7;
            pVh[d * 216 + c] = z;
            pVl[d * 216 + c] = z;
        }
    }
    CP_WAIT0();
    __syncthreads();

    const int mt = bx * 4 + w;
    if (mt >= 13) return;   // no further CTA-wide syncs

    // Q fragments from gmem (rows clamped; out-of-range rows discarded on store)
    const int qr0 = mt * 16 + g, qr1 = qr0 + 8;
    const int gr0 = b * POMO + (qr0 < POMO ? qr0 : POMO - 1);
    const int gr1 = b * POMO + (qr1 < POMO ? qr1 : POMO - 1);
    const unsigned* Qhu = (const unsigned*)Qh;
    const unsigned* Qlu = (const unsigned*)Ql;
    unsigned aQh[2][4], aQl[2][4];
#pragma unroll
    for (int ks = 0; ks < 2; ++ks) {
        const size_t s0 = (((size_t)gr0 * EMB + h * HD + ks * 16) >> 1) + tig;
        const size_t s1 = (((size_t)gr1 * EMB + h * HD + ks * 16) >> 1) + tig;
        aQh[ks][0] = Qhu[s0]; aQh[ks][1] = Qhu[s1];
        aQh[ks][2] = Qhu[s0 + 4]; aQh[ks][3] = Qhu[s1 + 4];
        aQl[ks][0] = Qlu[s0]; aQl[ks][1] = Qlu[s1];
        aQl[ks][2] = Qlu[s0 + 4]; aQl[ks][3] = Qlu[s1 + 4];
    }

    float Oacc[4][4];
#pragma unroll
    for (int i = 0; i < 4; ++i)
#pragma unroll
        for (int j = 0; j < 4; ++j) Oacc[i][j] = 0.f;
    float mx0 = -1e30f, mx1 = -1e30f, l0 = 0.f, l1 = 0.f;
    const float scale = 0.17677669529663687f;   // 1/sqrt(32)
    const int lr = w * 16 + g;

#pragma unroll 1
    for (int kt = 0; kt < 13; ++kt) {
        // ---- S = Q K^T (x3) ----
        float c0[4] = {0.f, 0.f, 0.f, 0.f}, c1[4] = {0.f, 0.f, 0.f, 0.f};
#pragma unroll
        for (int nt = 0; nt < 2; ++nt) {
            float* cc = nt ? c1 : c0;
            const int key = kt * 16 + nt * 8 + g;
#pragma unroll
            for (int ks = 0; ks < 2; ++ks) {
                const unsigned base = key * AT_KP + ks * 8 + tig;
                unsigned bh[2] = { sKh[base], sKh[base + 4] };
                unsigned bl[2] = { sKl[base], sKl[base + 4] };
                mma_bf16(cc, aQh[ks], bh);
                mma_bf16(cc, aQl[ks], bh);
                mma_bf16(cc, aQh[ks], bl);
            }
        }
        // ---- scale + mask ----
        float sv0[4], sv1[4];
        const int kbase = kt * 16 + 2 * tig;
#pragma unroll
        for (int j = 0; j < 4; ++j) {
            const int key = kbase + (j >> 1) * 8 + (j & 1);
            float mk0, mk1;
            if (key < PROB)      { mk0 = sMk[lr * AT_MP + key]; mk1 = sMk[(lr + 8) * AT_MP + key]; }
            else if (key == PROB){ mk0 = 0.f; mk1 = 0.f; }
            else                 { mk0 = -1e30f; mk1 = -1e30f; }
            const float* cc = (j < 2) ? c0 : c1;
            sv0[j] = fmaf(cc[j & 1], scale, mk0);
            sv1[j] = fmaf(cc[2 + (j & 1)], scale, mk1);
        }
        // ---- online softmax (quad-uniform max) ----
        float m0 = fmaxf(fmaxf(sv0[0], sv0[1]), fmaxf(sv0[2], sv0[3]));
        float m1 = fmaxf(fmaxf(sv1[0], sv1[1]), fmaxf(sv1[2], sv1[3]));
        m0 = fmaxf(m0, __shfl_xor_sync(0xffffffffu, m0, 1));
        m0 = fmaxf(m0, __shfl_xor_sync(0xffffffffu, m0, 2));
        m1 = fmaxf(m1, __shfl_xor_sync(0xffffffffu, m1, 1));
        m1 = fmaxf(m1, __shfl_xor_sync(0xffffffffu, m1, 2));
        if (m0 > mx0) {
            const float a = __expf(mx0 - m0); mx0 = m0; l0 *= a;
#pragma unroll
            for (int vd = 0; vd < 4; ++vd) { Oacc[vd][0] *= a; Oacc[vd][1] *= a; }
        }
        if (m1 > mx1) {
            const float a = __expf(mx1 - m1); mx1 = m1; l1 *= a;
#pragma unroll
            for (int vd = 0; vd < 4; ++vd) { Oacc[vd][2] *= a; Oacc[vd][3] *= a; }
        }
        float p0[4], p1[4];
#pragma unroll
        for (int j = 0; j < 4; ++j) {
            p0[j] = __expf(sv0[j] - mx0);
            p1[j] = __expf(sv1[j] - mx1);
        }
        l0 += p0[0] + p0[1] + p0[2] + p0[3];   // per-thread partial (4 of 16 keys)
        l1 += p1[0] + p1[1] + p1[2] + p1[3];
        // ---- pack P fragments (c-frag layout == a-frag layout) ----
        unsigned aPh[4], aPl[4];
        pks(p0[0], p0[1], aPh[0], aPl[0]);
        pks(p1[0], p1[1], aPh[1], aPl[1]);
        pks(p0[2], p0[3], aPh[2], aPl[2]);
        pks(p1[2], p1[3], aPh[3], aPl[3]);
        // ---- O += P V ----
#pragma unroll
        for (int vd = 0; vd < 4; ++vd) {
            const unsigned base = (vd * 8 + g) * AT_VP + kt * 8 + tig;
            unsigned bh[2] = { sVh[base], sVh[base + 4] };
            unsigned bl[2] = { sVl[base], sVl[base + 4] };
            mma_bf16(Oacc[vd], aPh, bh);
            mma_bf16(Oacc[vd], aPl, bh);
            mma_bf16(Oacc[vd], aPh, bl);
        }
    }

    // ---- FIX: reduce softmax denominators across the quad (tig lanes).
    // Oacc is an mma C-fragment (already fully reduced over keys); l0/l1 were
    // per-thread partials over this thread's 4-of-16 key columns. mx is
    // quad-uniform, so partials are compatible and simply sum.
    l0 += __shfl_xor_sync(0xffffffffu, l0, 1);
    l0 += __shfl_xor_sync(0xffffffffu, l0, 2);
    l1 += __shfl_xor_sync(0xffffffffu, l1, 1);
    l1 += __shfl_xor_sync(0xffffffffu, l1, 2);

    // ---- normalize + store hi/lo ----
    const float i0 = 1.f / l0, i1 = 1.f / l1;
#pragma unroll
    for (int vd = 0; vd < 4; ++vd) {
        const int col = h * HD + vd * 8 + 2 * tig;
        if (qr0 < POMO) {
            const size_t o = (size_t)(b * POMO + qr0) * EMB + col;
            const float v0 = Oacc[vd][0] * i0, v1 = Oacc[vd][1] * i0;
            __nv_bfloat16 h0, lo0, h1, lo1;
            split2(v0, h0, lo0); split2(v1, h1, lo1);
            *(__nv_bfloat162*)(Oh + o) = __nv_bfloat162(h0, h1);
            *(__nv_bfloat162*)(Ol + o) = __nv_bfloat162(lo0, lo1);
        }
        if (qr1 < POMO) {
            const size_t o = (size_t)(b * POMO + qr1) * EMB + col;
            const float v0 = Oacc[vd][2] * i1, v1 = Oacc[vd][3] * i1;
            __nv_bfloat16 h0, lo0, h1, lo1;
            split2(v0, h0, lo0); split2(v1, h1, lo1);
            *(__nv_bfloat162*)(Oh + o) = __nv_bfloat162(h0, h1);
            *(__nv_bfloat162*)(Ol + o) = __nv_bfloat162(lo0, lo1);
        }
    }
}

// ---------------------------------------------------------------------------
// score2 bf16x3: per-batch NT GEMM MH[200,512] @ nodes[:200,512]^T with
// /sqrt(EMB) -> 10*tanh -> +mask epilogue. BM=64, BN=128.
// ---------------------------------------------------------------------------
#define S_ATI (64 * KP)
#define S_BTI (128 * KP)

__global__ __launch_bounds__(256, 2) void score2_bf16(
    const __nv_bfloat16* __restrict__ MHh, const __nv_bfloat16* __restrict__ MHl,
    const __nv_bfloat16* __restrict__ Nh,  const __nv_bfloat16* __restrict__ Nl,
    const float* __restrict__ mask, float* __restrict__ out)
{
    extern __shared__ unsigned smu[];
    unsigned* sAh = smu;
    unsigned* sAl = smu + GST * S_ATI;
    unsigned* sBh = smu + 2 * GST * S_ATI;
    unsigned* sBl = smu + 2 * GST * S_ATI + GST * S_BTI;

    const int tid  = threadIdx.x;
    const int lane = tid & 31, warp = tid >> 5;
    const int g    = lane >> 2, tig = lane & 3;
    const int wm   = warp >> 2, wn  = warp & 3;
    const int b    = blockIdx.z;
    const int bm   = blockIdx.y * 64, bn = blockIdx.x * 128;

    const int rb = tid >> 1, half = tid & 1;
    const int ra = (tid & 127) >> 1;

    auto load_tile = [&](int st, int t) {
        const int k0 = t << 4;
        int gb = bn + rb; if (gb >= PROB) gb = PROB - 1;
        const size_t go = ((size_t)b * NNODE + gb) * EMB + k0 + half * 8;
        const unsigned ob = st * S_BTI + rb * KP + half * 4;
        cp16(smem_u32(sBh + ob), Nh + go);
        cp16(smem_u32(sBl + ob), Nl + go);
        if (tid < 128) {
            int ga = bm + ra; if (ga >= POMO) ga = POMO - 1;
            const size_t ao = ((size_t)b * POMO + ga) * EMB + k0 + half * 8;
            const unsigned oa = st * S_ATI + ra * KP + half * 4;
            cp16(smem_u32(sAh + oa), MHh + ao);
            cp16(smem_u32(sAl + oa), MHl + ao);
        }
    };

    float acc[2][4][4];
#pragma unroll
    for (int i = 0; i < 2; ++i)
#pragma unroll
        for (int j = 0; j < 4; ++j)
#pragma unroll
            for (int t = 0; t < 4; ++t) acc[i][j][t] = 0.f;

    const int S = EMB / 16;
#pragma unroll
    for (int t = 0; t < GST - 1; ++t) {
        if (t < S) load_tile(t, t);
        CP_COMMIT();
    }

    for (int s = 0; s < S; ++s) {
        CP_WAIT1();
        __syncthreads();
        const int nt = s + GST - 1;
        if (nt < S) load_tile(nt % GST, nt);
        CP_COMMIT();

        const unsigned* As_ = sAh + (s % GST) * S_ATI;
        const unsigned* Al_ = sAl + (s % GST) * S_ATI;
        const unsigned* Bs_ = sBh + (s % GST) * S_BTI;
        const unsigned* Bl_ = sBl + (s % GST) * S_BTI;

        unsigned ah[2][4], bh[4][2];
#pragma unroll
        for (int mf = 0; mf < 2; ++mf) {
            const int mr = wm * 32 + mf * 16 + g;
            ah[mf][0] = As_[mr * KP + tig];
            ah[mf][1] = As_[(mr + 8) * KP + tig];
            ah[mf][2] = As_[mr * KP + tig + 4];
            ah[mf][3] = As_[(mr + 8) * KP + tig + 4];
        }
#pragma unroll
        for (int nf = 0; nf < 4; ++nf) {
            const int nc = wn * 32 + nf * 8 + g;
            bh[nf][0] = Bs_[nc * KP + tig];
            bh[nf][1] = Bs_[nc * KP + tig + 4];
        }
#pragma unroll
        for (int mf = 0; mf < 2; ++mf)
#pragma unroll
            for (int nf = 0; nf < 4; ++nf)
                mma_bf16(acc[mf][nf], ah[mf], bh[nf]);

        unsigned al[2][4];
#pragma unroll
        for (int mf = 0; mf < 2; ++mf) {
            const int mr = wm * 32 + mf * 16 + g;
            al[mf][0] = Al_[mr * KP + tig];
            al[mf][1] = Al_[(mr + 8) * KP + tig];
            al[mf][2] = Al_[mr * KP + tig + 4];
            al[mf][3] = Al_[(mr + 8) * KP + tig + 4];
        }
#pragma unroll
        for (int mf = 0; mf < 2; ++mf)
#pragma unroll
            for (int nf = 0; nf < 4; ++nf)
                mma_bf16(acc[mf][nf], al[mf], bh[nf]);

        unsigned bl[4][2];
#pragma unroll
        for (int nf = 0; nf < 4; ++nf) {
            const int nc = wn * 32 + nf * 8 + g;
            bl[nf][0] = Bl_[nc * KP + tig];
            bl[nf][1] = Bl_[nc * KP + tig + 4];
        }
#pragma unroll
        for (int mf = 0; mf < 2; ++mf)
#pragma unroll
            for (int nf = 0; nf < 4; ++nf)
                mma_bf16(acc[mf][nf], ah[mf], bl[nf]);
    }

    const float inv_sqrt_emb = 0.04419417382415922f;
#pragma unroll
    for (int mf = 0; mf < 2; ++mf) {
#pragma unroll
        for (int nf = 0; nf < 4; ++nf) {
#pragma unroll
            for (int t = 0; t < 4; ++t) {
                const int r = bm + wm * 32 + mf * 16 + g + ((t >> 1) << 3);
                const int c = bn + wn * 32 + nf * 8 + 2 * tig + (t & 1);
                if (r < POMO && c < PROB) {
                    const size_t off = ((size_t)b * POMO + r) * PROB + c;
                    out[off] = 10.f * tanhf(acc[mf][nf][t] * inv_sqrt_emb) + mask[off];
                }
            }
        }
    }
}

// ---------------------------------------------------------------------------
// In-place row softmax over 200 columns, one warp per row.
// ---------------------------------------------------------------------------
__global__ __launch_bounds__(256) void softmax_kernel(float* __restrict__ out)
{
    const int row  = blockIdx.x * 8 + (threadIdx.x >> 5);
    const int lane = threadIdx.x & 31;
    float* p = out + (size_t)row * PROB;

    float v[7];
    float mx = -1e30f;
#pragma unroll
    for (int i = 0; i < 7; ++i) {
        int c = lane + (i << 5);
        v[i] = (c < PROB) ? p[c] : -1e30f;
        mx = fmaxf(mx, v[i]);
    }
#pragma unroll
    for (int off = 16; off; off >>= 1)
        mx = fmaxf(mx, __shfl_xor_sync(0xffffffffu, mx, off));

    float sum = 0.f;
#pragma unroll
    for (int i = 0; i < 7; ++i) { v[i] = __expf(v[i] - mx); sum += v[i]; }
#pragma unroll
    for (int off = 16; off; off >>= 1)
        sum += __shfl_xor_sync(0xffffffffu, sum, off);

    float inv = 1.f / sum;
#pragma unroll
    for (int i = 0; i < 7; ++i) {
        int c = lane + (i << 5);
        if (c < PROB) p[c] = v[i] * inv;
    }
}

// ---------------------------------------------------------------------------
// Launch
// ---------------------------------------------------------------------------
extern "C" void kernel_launch(void* const* d_in, const int* in_sizes, int n_in,
                              void* d_out, int out_size)
{
    const float* nodes = (const float*)d_in[0];
    const float* q1    = (const float*)d_in[1];
    const float* lastn = (const float*)d_in[2];
    const float* mask  = (const float*)d_in[3];
    const float* Wqf   = (const float*)d_in[4];
    const float* Wql   = (const float*)d_in[5];
    const float* Wk    = (const float*)d_in[6];
    const float* Wv    = (const float*)d_in[7];
    const float* Wc    = (const float*)d_in[8];
    const float* bc    = (const float*)d_in[9];
    float* out = (float*)d_out;

    __nv_bfloat16 *nh, *nl, *q1h, *q1l, *lnh, *lnl, *Oh, *Ol, *MHh, *MHl;
    __nv_bfloat16 *Khb, *Klb, *Vhb, *Vlb, *Qhb, *Qlb;
    __nv_bfloat16 *Wkh, *Wkl, *Wvh, *Wvl, *Wqfh, *Wqfl, *Wqlh, *Wqll, *Wch, *Wcl;
    cudaGetSymbolAddress((void**)&nh,   g_nh);   cudaGetSymbolAddress((void**)&nl,   g_nl);
    cudaGetSymbolAddress((void**)&q1h,  g_q1h);  cudaGetSymbolAddress((void**)&q1l,  g_q1l);
    cudaGetSymbolAddress((void**)&lnh,  g_lnh);  cudaGetSymbolAddress((void**)&lnl,  g_lnl);
    cudaGetSymbolAddress((void**)&Oh,   g_Oh);   cudaGetSymbolAddress((void**)&Ol,   g_Ol);
    cudaGetSymbolAddress((void**)&MHh,  g_MHh);  cudaGetSymbolAddress((void**)&MHl,  g_MHl);
    cudaGetSymbolAddress((void**)&Khb,  g_Kh);   cudaGetSymbolAddress((void**)&Klb,  g_Kl);
    cudaGetSymbolAddress((void**)&Vhb,  g_Vh);   cudaGetSymbolAddress((void**)&Vlb,  g_Vl);
    cudaGetSymbolAddress((void**)&Qhb,  g_Qh);   cudaGetSymbolAddress((void**)&Qlb,  g_Ql);
    cudaGetSymbolAddress((void**)&Wkh,  g_Wkh);  cudaGetSymbolAddress((void**)&Wkl,  g_Wkl);
    cudaGetSymbolAddress((void**)&Wvh,  g_Wvh);  cudaGetSymbolAddress((void**)&Wvl,  g_Wvl);
    cudaGetSymbolAddress((void**)&Wqfh, g_Wqfh); cudaGetSymbolAddress((void**)&Wqfl, g_Wqfl);
    cudaGetSymbolAddress((void**)&Wqlh, g_Wqlh); cudaGetSymbolAddress((void**)&Wqll, g_Wqll);
    cudaGetSymbolAddress((void**)&Wch,  g_Wch);  cudaGetSymbolAddress((void**)&Wcl,  g_Wcl);

    const int gemm_smem = 4 * GST * ATI * 4;                       // 73728
    cudaFuncSetAttribute(gemm_bf16x3,
                         cudaFuncAttributeMaxDynamicSharedMemorySize, gemm_smem);
    const int s2_smem = (2 * GST * S_ATI + 2 * GST * S_BTI) * 4;   // 55296
    cudaFuncSetAttribute(score2_bf16,
                         cudaFuncAttributeMaxDynamicSharedMemorySize, s2_smem);
    cudaFuncSetAttribute(attn_mma,
                         cudaFuncAttributeMaxDynamicSharedMemorySize, ATTN_SMEM);

    // --- split-convert inputs ---
    const int nNodes = BB * NNODE * EMB, nAct = BB * POMO * EMB;
    convsplit<<<(nNodes / 4 + 255) / 256, 256>>>(nodes, nh,  nl,  nNodes);
    convsplit<<<(nAct   / 4 + 255) / 256, 256>>>(q1,    q1h, q1l, nAct);
    convsplit<<<(nAct   / 4 + 255) / 256, 256>>>(lastn, lnh, lnl, nAct);
    dim3 tg(16, 16), tb(32, 8);
    transconv512<<<tg, tb>>>(Wk,  Wkh,  Wkl);
    transconv512<<<tg, tb>>>(Wv,  Wvh,  Wvl);
    transconv512<<<tg, tb>>>(Wqf, Wqfh, Wqfl);
    transconv512<<<tg, tb>>>(Wql, Wqlh, Wqll);
    transconv512<<<tg, tb>>>(Wc,  Wch,  Wcl);

    // --- projections (emit bf16 hi/lo) ---
    dim3 gKV(EMB / 128, (BB * NNODE + 127) / 128);  // 4 x 101
    gemm_bf16x3<<<gKV, 256, gemm_smem>>>(nh, nl, Wkh, Wkl,
        nullptr, nullptr, nullptr, nullptr, nullptr, nullptr, Khb, Klb,
        BB * NNODE, EMB, EMB);
    gemm_bf16x3<<<gKV, 256, gemm_smem>>>(nh, nl, Wvh, Wvl,
        nullptr, nullptr, nullptr, nullptr, nullptr, nullptr, Vhb, Vlb,
        BB * NNODE, EMB, EMB);

    dim3 gQ(EMB / 128, (BB * POMO) / 128);          // 4 x 100
    gemm_bf16x3<<<gQ, 256, gemm_smem>>>(q1h, q1l, Wqfh, Wqfl,
        lnh, lnl, Wqlh, Wqll, nullptr, nullptr, Qhb, Qlb,
        BB * POMO, EMB, EMB);

    // --- tensor-core flash attention ---
    attn_mma<<<dim3(4, NH, BB), 128, ATTN_SMEM>>>(Qhb, Qlb, Khb, Klb,
                                                  Vhb, Vlb, mask, Oh, Ol);

    // --- Wc projection (emit bf16 split for score2) ---
    gemm_bf16x3<<<gQ, 256, gemm_smem>>>(Oh, Ol, Wch, Wcl,
        nullptr, nullptr, nullptr, nullptr, bc, nullptr, MHh, MHl,
        BB * POMO, EMB, EMB);

    // --- score2 + softmax ---
    dim3 gS(2, 4, BB);
    score2_bf16<<<gS, 256, s2_smem>>>(MHh, MHl, nh, nl, mask, out);

    softmax_kernel<<<(BB * POMO) / 8, 256>>>(out);
}